// round 2
// baseline (speedup 1.0000x reference)
#include <cuda_runtime.h>
#include <math.h>
#include <stdint.h>

#define EMAX 250000
#define NMAX 25000

#define INV_NN   0.51298917604257706f   // 1/sqrt(3.8)
#define INV3     0.57735026918962576f
#define INV112   0.89285714285714285f   // 1/1.12
#define S3       1.7320508075688772f
#define S5       2.2360679774997896f
#define S7       2.6457513110645907f
#define S15      3.8729833462074170f
#define S105     10.246950765959598f
#define C358     2.0916500663351889f
#define C218     1.6201851746019651f
#define RS3      0.57735026918962576f
#define RS5      0.44721359549995794f
#define RS7      0.37796447300922720f
#define SCALE1   (INV3 * 0.5f / 16.0f * INV_NN)
#define SCALE2   (INV3 / 128.0f * INV_NN)

typedef unsigned long long ull;

// ---------------------------------------------------------------------------
// Scratch
// ---------------------------------------------------------------------------
__device__ __align__(16) float g_sh   [EMAX * 16];
__device__ __align__(16) float g_x    [NMAX * 16];
__device__ __align__(16) float g_dots [EMAX * 4];
__device__ __align__(16) float g_basis[EMAX * 4];
__device__ int   g_hist[NMAX];
__device__ int   g_off [NMAX + 1];
__device__ int   g_cur [NMAX];
__device__ int   g_perm[EMAX];
__device__ __align__(16) float g_T   [(size_t)NMAX * 1024];
__device__ __align__(16) float g_Wre [1024 * 96];
__device__ __align__(16) float g_h   [NMAX * 96];
__device__ __align__(16) float g_z   [(size_t)NMAX * 256];

// f32x2 packed helpers
__device__ __forceinline__ ull pk2(float lo, float hi) {
    ull r; asm("mov.b64 %0,{%1,%2};" : "=l"(r) : "f"(lo), "f"(hi)); return r;
}
__device__ __forceinline__ void upk2(ull v, float& lo, float& hi) {
    asm("mov.b64 {%0,%1},%2;" : "=f"(lo), "=f"(hi) : "l"(v));
}
#define FMA2(d, a, b, c) asm("fma.rn.f32x2 %0,%1,%2,%3;" : "=l"(d) : "l"(a), "l"(b), "l"(c))
#define MUL2(d, a, b)    asm("mul.rn.f32x2 %0,%1,%2;"    : "=l"(d) : "l"(a), "l"(b))

// ---------------------------------------------------------------------------
// K0: zero histogram
// ---------------------------------------------------------------------------
__global__ void k_zero(int N)
{
    int i = blockIdx.x * blockDim.x + threadIdx.x;
    if (i < N) g_hist[i] = 0;
}

// ---------------------------------------------------------------------------
// K1: spherical harmonics per edge + dst histogram (int atomics only)
// ---------------------------------------------------------------------------
__global__ void k_sh(const float* __restrict__ edge_vec,
                     const int*   __restrict__ edst, int E)
{
    int e = blockIdx.x * blockDim.x + threadIdx.x;
    if (e >= E) return;
    float x = edge_vec[e * 3 + 0];
    float y = edge_vec[e * 3 + 1];
    float z = edge_vec[e * 3 + 2];
    float inv = 1.0f / (sqrtf(x * x + y * y + z * z) + 1e-12f);
    x *= inv; y *= inv; z *= inv;
    float x2 = x * x, y2 = y * y, z2 = z * z;

    float4* shp = (float4*)&g_sh[(size_t)e * 16];
    shp[0] = make_float4(1.0f, S3 * x, S3 * y, S3 * z);
    shp[1] = make_float4(S15 * x * z, S15 * x * y,
                         0.5f * S5 * (2.0f * y2 - x2 - z2), S15 * y * z);
    shp[2] = make_float4(0.5f * S15 * (z2 - x2),
                         C358 * x * (3.0f * z2 - x2),
                         S105 * x * y * z,
                         C218 * x * (4.0f * y2 - z2 - x2));
    shp[3] = make_float4(0.5f * S7 * y * (2.0f * y2 - 3.0f * z2 - 3.0f * x2),
                         C218 * z * (4.0f * y2 - z2 - x2),
                         0.5f * S105 * y * (z2 - x2),
                         C358 * z * (z2 - 3.0f * x2));

    atomicAdd(&g_hist[edst[e]], 1);
}

// ---------------------------------------------------------------------------
// K2: exclusive scan, 25 elems/thread, one block
// ---------------------------------------------------------------------------
__global__ void __launch_bounds__(1024) k_scan(int E, int N)
{
    const int C = 25;
    int t = threadIdx.x;
    int base = t * C;
    int loc[C];
    int s = 0;
#pragma unroll
    for (int i = 0; i < C; i++) {
        int idx = base + i;
        int v = (idx < N) ? g_hist[idx] : 0;
        loc[i] = s; s += v;
    }
    __shared__ int wsum[32];
    __shared__ int wpre[32];
    int lane = t & 31, wid = t >> 5;
    int xv = s;
#pragma unroll
    for (int o = 1; o < 32; o <<= 1) {
        int tt = __shfl_up_sync(0xffffffffu, xv, o);
        if (lane >= o) xv += tt;
    }
    if (lane == 31) wsum[wid] = xv;
    __syncthreads();
    if (wid == 0) {
        int wv = wsum[lane];
        int xs = wv;
#pragma unroll
        for (int o = 1; o < 32; o <<= 1) {
            int tt = __shfl_up_sync(0xffffffffu, xs, o);
            if (lane >= o) xs += tt;
        }
        wpre[lane] = xs - wv;
    }
    __syncthreads();
    int texcl = (xv - s) + wpre[wid];
#pragma unroll
    for (int i = 0; i < C; i++) {
        int idx = base + i;
        if (idx < N) {
            int v = texcl + loc[i];
            g_off[idx] = v; g_cur[idx] = v;
        }
    }
    if (t == 0) g_off[N] = E;
}

// ---------------------------------------------------------------------------
// K3: counting-sort placement
// ---------------------------------------------------------------------------
__global__ void k_place(const int* __restrict__ edst, int E)
{
    int e = blockIdx.x * blockDim.x + threadIdx.x;
    if (e >= E) return;
    int pos = atomicAdd(&g_cur[edst[e]], 1);
    g_perm[pos] = e;
}

// ---------------------------------------------------------------------------
// K4: x[n,c] = sum over edges->n of sh  (gather, no atomics). 16 lanes/node.
// ---------------------------------------------------------------------------
__global__ void __launch_bounds__(256) k_x(int N)
{
    int n = blockIdx.x * 16 + (threadIdx.x >> 4);
    int c = threadIdx.x & 15;
    if (n >= N) return;
    int beg = g_off[n], end = g_off[n + 1];
    float acc = 0.f;
    for (int i = beg; i < end; i++) {
        int e = g_perm[i];
        acc += g_sh[(size_t)e * 16 + c];
    }
    g_x[n * 16 + c] = acc;
}

// ---------------------------------------------------------------------------
// K2b: reorder W1b [256,4*96] -> Wre [(c*4+p), k]
// ---------------------------------------------------------------------------
__global__ void k_reord(const float* __restrict__ W1b)
{
    int idx = blockIdx.x * blockDim.x + threadIdx.x;
    if (idx >= 1024 * 96) return;
    int kk = idx / 96;
    int k  = idx - kk * 96;
    int c  = kk >> 2;
    int p  = kk & 3;
    g_Wre[idx] = W1b[c * 384 + p * 96 + k];
}

// ---------------------------------------------------------------------------
// K5: per-edge dots + radial basis
// ---------------------------------------------------------------------------
__global__ void k_dotsb(const float* __restrict__ edge_len,
                        const int*  __restrict__ esrc, int E)
{
    int e = blockIdx.x * blockDim.x + threadIdx.x;
    if (e >= E) return;
    int src = esrc[e];
    const float4* shp = (const float4*)&g_sh[(size_t)e * 16];
    const float4* xp  = (const float4*)&g_x[(size_t)src * 16];
    float4 s0 = shp[0], s1 = shp[1], s2 = shp[2], s3 = shp[3];
    float4 x0 = xp[0],  x1 = xp[1],  x2 = xp[2],  x3 = xp[3];

    float d0 = x0.x * s0.x;
    float d1 = (x0.y * s0.y + x0.z * s0.z + x0.w * s0.w) * RS3;
    float d2 = (x1.x * s1.x + x1.y * s1.y + x1.z * s1.z + x1.w * s1.w + x2.x * s2.x) * RS5;
    float d3 = (x2.y * s2.y + x2.z * s2.z + x2.w * s2.w +
                x3.x * s3.x + x3.y * s3.y + x3.z * s3.z + x3.w * s3.w) * RS7;
    *(float4*)&g_dots[(size_t)e * 4] =
        make_float4(d0 * INV_NN, d1 * INV_NN, d2 * INV_NN, d3 * INV_NN);

    float len = edge_len[e];
    float t0 = len * 0.5f;
    float t1 = (len - 2.0f) * 0.5f;
    float t2 = (len - 4.0f) * 0.5f;
    *(float4*)&g_basis[(size_t)e * 4] =
        make_float4(expf(-t0 * t0) * INV112, expf(-t1 * t1) * INV112,
                    expf(-t2 * t2) * INV112, 0.f);
}

// ---------------------------------------------------------------------------
// K6: build T[n, c*4+p]; one warp per node
// ---------------------------------------------------------------------------
__global__ void __launch_bounds__(256) k_buildT(const float* __restrict__ W1a, int N)
{
    __shared__ float sW[768];
    for (int i = threadIdx.x; i < 768; i += 256) sW[i] = W1a[i];
    __syncthreads();

    int w = blockIdx.x * 8 + (threadIdx.x >> 5);
    int lane = threadIdx.x & 31;
    if (w >= N) return;
    int beg = g_off[w], end = g_off[w + 1];

    float wa0[8], wa1[8], wa2[8];
#pragma unroll
    for (int j = 0; j < 8; j++) {
        int c = j * 32 + lane;
        wa0[j] = sW[c]; wa1[j] = sW[256 + c]; wa2[j] = sW[512 + c];
    }
    float4 acc[8];
#pragma unroll
    for (int j = 0; j < 8; j++) acc[j] = make_float4(0.f, 0.f, 0.f, 0.f);

    for (int i = beg; i < end; i++) {
        int e = g_perm[i];
        float4 bs = *(const float4*)&g_basis[(size_t)e * 4];
        float4 dt = *(const float4*)&g_dots[(size_t)e * 4];
#pragma unroll
        for (int j = 0; j < 8; j++) {
            float h1 = fmaxf(fmaf(bs.x, wa0[j], fmaf(bs.y, wa1[j], bs.z * wa2[j])), 0.f);
            acc[j].x = fmaf(h1, dt.x, acc[j].x);
            acc[j].y = fmaf(h1, dt.y, acc[j].y);
            acc[j].z = fmaf(h1, dt.z, acc[j].z);
            acc[j].w = fmaf(h1, dt.w, acc[j].w);
        }
    }
    float* tp = &g_T[(size_t)w * 1024];
#pragma unroll
    for (int j = 0; j < 8; j++)
        *(float4*)&tp[(j * 32 + lane) * 4] = acc[j];
}

// ---------------------------------------------------------------------------
// K7: node GEMM h = T @ Wre * SCALE1, packed f32x2 FFMA2
//     BM=64, BN=96, BK=16, 128 threads, per-thread 8x6 (8x3 packed)
// ---------------------------------------------------------------------------
__global__ void __launch_bounds__(128) k_gemm(int M)
{
    __shared__ float2 As2[16][64];   // duplicated pairs (v,v), [k][m]
    __shared__ float  Bs[16 * 96];   // natural layout, [k][n]
    int tid = threadIdx.x;
    int m0 = blockIdx.x * 64;
    int cg = tid & 15;   // 16 col groups x 6 cols (3 packed)
    int rg = tid >> 4;   // 8 row groups x 8 rows

    ull acc[8][3];
#pragma unroll
    for (int i = 0; i < 8; i++)
#pragma unroll
        for (int j = 0; j < 3; j++) acc[i][j] = 0ull;

    // prefetch registers
    float4 aR[2];
    float4 bR[3];

    // initial load (kc = 0)
#pragma unroll
    for (int t = 0; t < 2; t++) {
        int q = tid + 128 * t;
        int row = q >> 2;
        int kq = (q & 3) << 2;
        int gm = m0 + row;
        aR[t] = (gm < M) ? *(const float4*)&g_T[(size_t)gm * 1024 + kq]
                         : make_float4(0.f, 0.f, 0.f, 0.f);
    }
#pragma unroll
    for (int j = 0; j < 3; j++)
        bR[j] = *(const float4*)&g_Wre[(tid + 128 * j) * 4];

    for (int kc = 0; kc < 1024; kc += 16) {
        __syncthreads();
        // store prefetched tiles
#pragma unroll
        for (int t = 0; t < 2; t++) {
            int q = tid + 128 * t;
            int row = q >> 2;
            int kq = (q & 3) << 2;
            As2[kq + 0][row] = make_float2(aR[t].x, aR[t].x);
            As2[kq + 1][row] = make_float2(aR[t].y, aR[t].y);
            As2[kq + 2][row] = make_float2(aR[t].z, aR[t].z);
            As2[kq + 3][row] = make_float2(aR[t].w, aR[t].w);
        }
#pragma unroll
        for (int j = 0; j < 3; j++)
            *(float4*)&Bs[(tid + 128 * j) * 4] = bR[j];
        __syncthreads();

        // prefetch next k-chunk
        int kn = kc + 16;
        if (kn < 1024) {
#pragma unroll
            for (int t = 0; t < 2; t++) {
                int q = tid + 128 * t;
                int row = q >> 2;
                int kq = (q & 3) << 2;
                int gm = m0 + row;
                aR[t] = (gm < M) ? *(const float4*)&g_T[(size_t)gm * 1024 + kn + kq]
                                 : make_float4(0.f, 0.f, 0.f, 0.f);
            }
#pragma unroll
            for (int j = 0; j < 3; j++)
                bR[j] = *(const float4*)&g_Wre[kn * 96 + (tid + 128 * j) * 4];
        }

        // compute
#pragma unroll
        for (int k = 0; k < 16; k++) {
            const ulonglong2* ap = (const ulonglong2*)&As2[k][rg * 8];
            ulonglong2 p0 = ap[0], p1 = ap[1], p2 = ap[2], p3 = ap[3];
            ull a[8] = {p0.x, p0.y, p1.x, p1.y, p2.x, p2.y, p3.x, p3.y};
            const ull* bp = (const ull*)&Bs[k * 96 + cg * 6];
            ull b[3] = {bp[0], bp[1], bp[2]};
#pragma unroll
            for (int i = 0; i < 8; i++)
#pragma unroll
                for (int j = 0; j < 3; j++)
                    FMA2(acc[i][j], a[i], b[j], acc[i][j]);
        }
    }

    ull sc = pk2(SCALE1, SCALE1);
#pragma unroll
    for (int i = 0; i < 8; i++) {
        int gm = m0 + rg * 8 + i;
        if (gm < M) {
#pragma unroll
            for (int j = 0; j < 3; j++) {
                ull r; MUL2(r, acc[i][j], sc);
                float lo, hi; upk2(r, lo, hi);
                *(float2*)&g_h[(size_t)gm * 96 + cg * 6 + 2 * j] = make_float2(lo, hi);
            }
        }
    }
}

// ---------------------------------------------------------------------------
// K8: per-node activation y, then z = W2b @ y
// ---------------------------------------------------------------------------
__global__ void __launch_bounds__(256) k_yz(const float* __restrict__ W2b, int N)
{
    __shared__ float sy[32][64];
    int n0 = blockIdx.x * 32;
    int tid = threadIdx.x;

    for (int q = tid; q < 2048; q += 256) {
        int node = q >> 6;
        int k = q & 63;
        int gn = n0 + node;
        float yv = 0.f;
        if (gn < N) {
            const float* hp = &g_h[(size_t)gn * 96];
            if (k < 32) {
                float s = hp[k];
                yv = (k < 16) ? fmaxf(s, 0.f) : fabsf(s);
            } else {
                int j = k - 32;
                float gv = hp[32 + j];
                float vv = hp[64 + j];
                float ga;
                if (j < 8)       ga = fmaxf(gv, 0.f);
                else if (j < 16) ga = tanhf(gv);
                else if (j < 24) ga = fmaxf(gv, 0.f);
                else             ga = tanhf(gv);
                yv = ga * vv;
            }
        }
        sy[node][k] = yv;
    }
    __syncthreads();

    int c = tid;
    float wreg[64];
#pragma unroll
    for (int k4 = 0; k4 < 16; k4++) {
        float4 v = *(const float4*)&W2b[c * 64 + k4 * 4];
        wreg[k4 * 4 + 0] = v.x; wreg[k4 * 4 + 1] = v.y;
        wreg[k4 * 4 + 2] = v.z; wreg[k4 * 4 + 3] = v.w;
    }
    for (int node = 0; node < 32; node++) {
        int gn = n0 + node;
        if (gn >= N) break;
        float s = 0.f;
#pragma unroll
        for (int k = 0; k < 64; k++) s = fmaf(wreg[k], sy[node][k], s);
        g_z[(size_t)gn * 256 + c] = s;
    }
}

// ---------------------------------------------------------------------------
// K9: final pass, warp per NODE over dst-sorted edges; no atomics
// ---------------------------------------------------------------------------
__global__ void __launch_bounds__(256) k_final(const float* __restrict__ W2a,
                                               const int* __restrict__ esrc,
                                               float* __restrict__ out, int N)
{
    __shared__ float sW[768];
    for (int i = threadIdx.x; i < 768; i += 256) sW[i] = W2a[i];
    __syncthreads();

    int w = blockIdx.x * 8 + (threadIdx.x >> 5);
    int lane = threadIdx.x & 31;
    if (w >= N) return;
    int beg = g_off[w], end = g_off[w + 1];

    float w0[8], w1[8], w2[8];
#pragma unroll
    for (int j = 0; j < 8; j++) {
        int c = j * 32 + lane;
        w0[j] = sW[c]; w1[j] = sW[256 + c]; w2[j] = sW[512 + c];
    }

    float sum = 0.f;
    for (int i = beg; i < end; i++) {
        int e = g_perm[i];
        int src = esrc[e];
        float4 bs = *(const float4*)&g_basis[(size_t)e * 4];
        const float* zp = &g_z[(size_t)src * 256];
#pragma unroll
        for (int j = 0; j < 8; j++) {
            int c = j * 32 + lane;
            float h2 = fmaxf(fmaf(bs.x, w0[j], fmaf(bs.y, w1[j], bs.z * w2[j])), 0.f);
            sum = fmaf(h2, zp[c], sum);
        }
    }
#pragma unroll
    for (int o = 16; o > 0; o >>= 1)
        sum += __shfl_down_sync(0xffffffffu, sum, o);
    if (lane == 0) out[w] = sum * SCALE2;
}

// ---------------------------------------------------------------------------
// Launch
// ---------------------------------------------------------------------------
extern "C" void kernel_launch(void* const* d_in, const int* in_sizes, int n_in,
                              void* d_out, int out_size)
{
    const float* edge_vec = (const float*)d_in[0];
    const float* edge_len = (const float*)d_in[1];
    const float* W1a      = (const float*)d_in[2];
    const float* W1b      = (const float*)d_in[3];
    const float* W2a      = (const float*)d_in[4];
    const float* W2b      = (const float*)d_in[5];
    const int*   esrc     = (const int*)d_in[6];
    const int*   edst     = (const int*)d_in[7];
    float* out = (float*)d_out;

    int E = in_sizes[1];
    int N = out_size;
    if (E > EMAX) E = EMAX;
    if (N > NMAX) N = NMAX;

    k_zero<<<(N + 255) / 256, 256>>>(N);
    k_sh<<<(E + 255) / 256, 256>>>(edge_vec, edst, E);
    k_reord<<<(1024 * 96 + 255) / 256, 256>>>(W1b);
    k_scan<<<1, 1024>>>(E, N);
    k_place<<<(E + 255) / 256, 256>>>(edst, E);
    k_x<<<(N + 15) / 16, 256>>>(N);
    k_dotsb<<<(E + 255) / 256, 256>>>(edge_len, esrc, E);
    k_buildT<<<(N + 7) / 8, 256>>>(W1a, N);
    k_gemm<<<(N + 63) / 64, 128>>>(N);
    k_yz<<<(N + 31) / 32, 256>>>(W2b, N);
    k_final<<<(N + 7) / 8, 256>>>(W2a, esrc, out, N);
}

// round 4
// speedup vs baseline: 1.0958x; 1.0958x over previous
#include <cuda_runtime.h>
#include <math.h>
#include <stdint.h>

#define EMAX 250000
#define NMAX 25000

#define INV_NN   0.51298917604257706f   // 1/sqrt(3.8)
#define INV3     0.57735026918962576f
#define INV112   0.89285714285714285f   // 1/1.12
#define S3       1.7320508075688772f
#define S5       2.2360679774997896f
#define S7       2.6457513110645907f
#define S15      3.8729833462074170f
#define S105     10.246950765959598f
#define C358     2.0916500663351889f
#define C218     1.6201851746019651f
#define RS3      0.57735026918962576f
#define RS5      0.44721359549995794f
#define RS7      0.37796447300922720f
#define SCALE1   (INV3 * 0.5f / 16.0f * INV_NN)
#define SCALE2   (INV3 / 128.0f * INV_NN)

// ---------------------------------------------------------------------------
// Scratch
// ---------------------------------------------------------------------------
__device__ __align__(16) float g_sh   [EMAX * 16];
__device__ __align__(16) float g_x    [NMAX * 16];
__device__ __align__(16) float g_dots [EMAX * 4];
__device__ __align__(16) float g_basis[EMAX * 4];
__device__ int   g_hist[NMAX];
__device__ int   g_off [NMAX + 1];
__device__ int   g_cur [NMAX];
__device__ int   g_perm[EMAX];
__device__ __align__(16) float g_T   [(size_t)NMAX * 1024];
// W1b hi/lo in mma-fragment order: float2 per (kc, ks, j, lane)
//   count = 32 * 4 * 12 * 32 = 49152 float2
__device__ __align__(16) float2 g_WBh [49152];
__device__ __align__(16) float2 g_WBl [49152];
__device__ __align__(16) float g_h   [NMAX * 96];
__device__ __align__(16) float g_z   [(size_t)NMAX * 256];

// ---------------------------------------------------------------------------
// mma.sync tf32 helper (m16n8k8)
// ---------------------------------------------------------------------------
#define MMA_TF32(d, a0, a1, a2, a3, b0, b1)                                   \
    asm volatile("mma.sync.aligned.m16n8k8.row.col.f32.tf32.tf32.f32 "        \
        "{%0,%1,%2,%3},{%4,%5,%6,%7},{%8,%9},{%0,%1,%2,%3};"                  \
        : "+f"((d)[0]), "+f"((d)[1]), "+f"((d)[2]), "+f"((d)[3])              \
        : "r"(a0), "r"(a1), "r"(a2), "r"(a3), "r"(b0), "r"(b1))

__device__ __forceinline__ float tf32_hi(float v) {
    return __uint_as_float(__float_as_uint(v) & 0xFFFFE000u);
}

// ---------------------------------------------------------------------------
// K0: zero histogram
// ---------------------------------------------------------------------------
__global__ void k_zero(int N)
{
    int i = blockIdx.x * blockDim.x + threadIdx.x;
    if (i < N) g_hist[i] = 0;
}

// ---------------------------------------------------------------------------
// K1: spherical harmonics per edge + dst histogram
// ---------------------------------------------------------------------------
__global__ void k_sh(const float* __restrict__ edge_vec,
                     const int*   __restrict__ edst, int E)
{
    int e = blockIdx.x * blockDim.x + threadIdx.x;
    if (e >= E) return;
    float x = edge_vec[e * 3 + 0];
    float y = edge_vec[e * 3 + 1];
    float z = edge_vec[e * 3 + 2];
    float inv = 1.0f / (sqrtf(x * x + y * y + z * z) + 1e-12f);
    x *= inv; y *= inv; z *= inv;
    float x2 = x * x, y2 = y * y, z2 = z * z;

    float4* shp = (float4*)&g_sh[(size_t)e * 16];
    shp[0] = make_float4(1.0f, S3 * x, S3 * y, S3 * z);
    shp[1] = make_float4(S15 * x * z, S15 * x * y,
                         0.5f * S5 * (2.0f * y2 - x2 - z2), S15 * y * z);
    shp[2] = make_float4(0.5f * S15 * (z2 - x2),
                         C358 * x * (3.0f * z2 - x2),
                         S105 * x * y * z,
                         C218 * x * (4.0f * y2 - z2 - x2));
    shp[3] = make_float4(0.5f * S7 * y * (2.0f * y2 - 3.0f * z2 - 3.0f * x2),
                         C218 * z * (4.0f * y2 - z2 - x2),
                         0.5f * S105 * y * (z2 - x2),
                         C358 * z * (z2 - 3.0f * x2));

    atomicAdd(&g_hist[edst[e]], 1);
}

// ---------------------------------------------------------------------------
// K2: exclusive scan — coalesced chunks
// ---------------------------------------------------------------------------
__global__ void __launch_bounds__(1024) k_scan(int E, int N)
{
    const int C = 25;
    int t = threadIdx.x, lane = t & 31, wid = t >> 5;
    int v[C];
#pragma unroll
    for (int i = 0; i < C; i++) {
        int idx = i * 1024 + t;
        v[i] = (idx < N) ? g_hist[idx] : 0;
    }
    __shared__ int wsum[32];
    __shared__ int wpre[32];
    int carry = 0;
#pragma unroll
    for (int i = 0; i < C; i++) {
        int x = v[i];
        int xv = x;
#pragma unroll
        for (int o = 1; o < 32; o <<= 1) {
            int tt = __shfl_up_sync(0xffffffffu, xv, o);
            if (lane >= o) xv += tt;
        }
        if (lane == 31) wsum[wid] = xv;
        __syncthreads();
        if (wid == 0) {
            int wv = wsum[lane];
            int xs = wv;
#pragma unroll
            for (int o = 1; o < 32; o <<= 1) {
                int tt = __shfl_up_sync(0xffffffffu, xs, o);
                if (lane >= o) xs += tt;
            }
            wpre[lane] = xs - wv;
        }
        __syncthreads();
        int excl = (xv - x) + wpre[wid] + carry;
        int idx = i * 1024 + t;
        if (idx < N) { g_off[idx] = excl; g_cur[idx] = excl; }
        carry += wpre[31] + wsum[31];
        __syncthreads();
    }
    if (t == 0) g_off[N] = E;
}

// ---------------------------------------------------------------------------
// K3: counting-sort placement
// ---------------------------------------------------------------------------
__global__ void k_place(const int* __restrict__ edst, int E)
{
    int e = blockIdx.x * blockDim.x + threadIdx.x;
    if (e >= E) return;
    int pos = atomicAdd(&g_cur[edst[e]], 1);
    g_perm[pos] = e;
}

// ---------------------------------------------------------------------------
// K4: x[n,c] gather-sum
// ---------------------------------------------------------------------------
__global__ void __launch_bounds__(256) k_x(int N)
{
    int n = blockIdx.x * 16 + (threadIdx.x >> 4);
    int c = threadIdx.x & 15;
    if (n >= N) return;
    int beg = g_off[n], end = g_off[n + 1];
    float acc = 0.f;
    for (int i = beg; i < end; i++) {
        int e = g_perm[i];
        acc += g_sh[(size_t)e * 16 + c];
    }
    g_x[n * 16 + c] = acc;
}

// ---------------------------------------------------------------------------
// K2b: W1b -> fragment-ordered hi/lo split (for mma.sync B operand)
//   frag element b0: kk = kc*32 + ks*8 + (lane&3), n = j*8 + (lane>>2)
//                b1: kk + 4, same n
// ---------------------------------------------------------------------------
__global__ void k_reord(const float* __restrict__ W1b)
{
    int idx = blockIdx.x * blockDim.x + threadIdx.x;
    if (idx >= 49152) return;
    int lane = idx & 31;
    int t = idx >> 5;          // 0..1535
    int j = t % 12;
    int t2 = t / 12;           // 0..127
    int ks = t2 & 3;
    int kc = t2 >> 2;
    int n = j * 8 + (lane >> 2);
    int kk0 = kc * 32 + ks * 8 + (lane & 3);
    int kk1 = kk0 + 4;
    int c0 = kk0 >> 2, p0 = kk0 & 3;
    int c1 = kk1 >> 2, p1 = kk1 & 3;
    float v0 = W1b[c0 * 384 + p0 * 96 + n];
    float v1 = W1b[c1 * 384 + p1 * 96 + n];
    float h0 = tf32_hi(v0);
    float h1 = tf32_hi(v1);
    g_WBh[idx] = make_float2(h0, h1);
    g_WBl[idx] = make_float2(v0 - h0, v1 - h1);
}

// ---------------------------------------------------------------------------
// K5: per-edge dots + radial basis
// ---------------------------------------------------------------------------
__global__ void k_dotsb(const float* __restrict__ edge_len,
                        const int*  __restrict__ esrc, int E)
{
    int e = blockIdx.x * blockDim.x + threadIdx.x;
    if (e >= E) return;
    int src = esrc[e];
    const float4* shp = (const float4*)&g_sh[(size_t)e * 16];
    const float4* xp  = (const float4*)&g_x[(size_t)src * 16];
    float4 s0 = shp[0], s1 = shp[1], s2 = shp[2], s3 = shp[3];
    float4 x0 = xp[0],  x1 = xp[1],  x2 = xp[2],  x3 = xp[3];

    float d0 = x0.x * s0.x;
    float d1 = (x0.y * s0.y + x0.z * s0.z + x0.w * s0.w) * RS3;
    float d2 = (x1.x * s1.x + x1.y * s1.y + x1.z * s1.z + x1.w * s1.w + x2.x * s2.x) * RS5;
    float d3 = (x2.y * s2.y + x2.z * s2.z + x2.w * s2.w +
                x3.x * s3.x + x3.y * s3.y + x3.z * s3.z + x3.w * s3.w) * RS7;
    *(float4*)&g_dots[(size_t)e * 4] =
        make_float4(d0 * INV_NN, d1 * INV_NN, d2 * INV_NN, d3 * INV_NN);

    float len = edge_len[e];
    float t0 = len * 0.5f;
    float t1 = (len - 2.0f) * 0.5f;
    float t2 = (len - 4.0f) * 0.5f;
    *(float4*)&g_basis[(size_t)e * 4] =
        make_float4(expf(-t0 * t0) * INV112, expf(-t1 * t1) * INV112,
                    expf(-t2 * t2) * INV112, 0.f);
}

// ---------------------------------------------------------------------------
// K6: build T[n, c*4+p]; one warp per node
// ---------------------------------------------------------------------------
__global__ void __launch_bounds__(256) k_buildT(const float* __restrict__ W1a, int N)
{
    __shared__ float sW[768];
    for (int i = threadIdx.x; i < 768; i += 256) sW[i] = W1a[i];
    __syncthreads();

    int w = blockIdx.x * 8 + (threadIdx.x >> 5);
    int lane = threadIdx.x & 31;
    if (w >= N) return;
    int beg = g_off[w], end = g_off[w + 1];

    float wa0[8], wa1[8], wa2[8];
#pragma unroll
    for (int j = 0; j < 8; j++) {
        int c = j * 32 + lane;
        wa0[j] = sW[c]; wa1[j] = sW[256 + c]; wa2[j] = sW[512 + c];
    }
    float4 acc[8];
#pragma unroll
    for (int j = 0; j < 8; j++) acc[j] = make_float4(0.f, 0.f, 0.f, 0.f);

    for (int i = beg; i < end; i++) {
        int e = g_perm[i];
        float4 bs = *(const float4*)&g_basis[(size_t)e * 4];
        float4 dt = *(const float4*)&g_dots[(size_t)e * 4];
#pragma unroll
        for (int j = 0; j < 8; j++) {
            float h1 = fmaxf(fmaf(bs.x, wa0[j], fmaf(bs.y, wa1[j], bs.z * wa2[j])), 0.f);
            acc[j].x = fmaf(h1, dt.x, acc[j].x);
            acc[j].y = fmaf(h1, dt.y, acc[j].y);
            acc[j].z = fmaf(h1, dt.z, acc[j].z);
            acc[j].w = fmaf(h1, dt.w, acc[j].w);
        }
    }
    float* tp = &g_T[(size_t)w * 1024];
#pragma unroll
    for (int j = 0; j < 8; j++)
        *(float4*)&tp[(j * 32 + lane) * 4] = acc[j];
}

// ---------------------------------------------------------------------------
// K7: node GEMM h = T @ W^T * SCALE1 via 3xTF32 mma.sync (m16n8k8)
//     CTA: 256 thr (8 warps), tile M=128 (16 rows/warp) x N=96, BK=32
// ---------------------------------------------------------------------------
#define APAD 36
#define GM_SMEM (2 * 128 * APAD * 4 + 2 * 1536 * 8)   // 36864 + 24576 = 61440

__global__ void __launch_bounds__(256) k_gemm_mma(int M)
{
    extern __shared__ float sm[];
    float*  Ahi = sm;                          // [128][36]
    float*  Alo = sm + 128 * APAD;
    float2* Bh  = (float2*)(sm + 2 * 128 * APAD);   // [1536]
    float2* Bl  = Bh + 1536;

    int tid = threadIdx.x, wid = tid >> 5, lane = tid & 31;
    int m0 = blockIdx.x * 128;

    float acc[12][4];
#pragma unroll
    for (int j = 0; j < 12; j++)
#pragma unroll
        for (int q = 0; q < 4; q++) acc[j][q] = 0.f;

    float4 aR[4], bhR[3], blR[3];

    // prefetch chunk 0
#pragma unroll
    for (int it = 0; it < 4; it++) {
        int idx = tid + 256 * it;
        int r = idx >> 3, c4 = idx & 7;
        int gm = m0 + r;
        aR[it] = (gm < M) ? *(const float4*)&g_T[(size_t)gm * 1024 + c4 * 4]
                          : make_float4(0.f, 0.f, 0.f, 0.f);
    }
#pragma unroll
    for (int it = 0; it < 3; it++) {
        bhR[it] = ((const float4*)g_WBh)[tid + 256 * it];
        blR[it] = ((const float4*)g_WBl)[tid + 256 * it];
    }

    for (int kc = 0; kc < 32; kc++) {
        __syncthreads();
        // store staged tile (split A into hi/lo)
#pragma unroll
        for (int it = 0; it < 4; it++) {
            int idx = tid + 256 * it;
            int r = idx >> 3, c4 = idx & 7;
            float4 v = aR[it];
            float4 hi = make_float4(tf32_hi(v.x), tf32_hi(v.y),
                                    tf32_hi(v.z), tf32_hi(v.w));
            float4 lo = make_float4(v.x - hi.x, v.y - hi.y,
                                    v.z - hi.z, v.w - hi.w);
            *(float4*)&Ahi[r * APAD + c4 * 4] = hi;
            *(float4*)&Alo[r * APAD + c4 * 4] = lo;
        }
#pragma unroll
        for (int it = 0; it < 3; it++) {
            ((float4*)Bh)[tid + 256 * it] = bhR[it];
            ((float4*)Bl)[tid + 256 * it] = blR[it];
        }
        __syncthreads();

        // prefetch next chunk
        if (kc < 31) {
            int kn = kc + 1;
#pragma unroll
            for (int it = 0; it < 4; it++) {
                int idx = tid + 256 * it;
                int r = idx >> 3, c4 = idx & 7;
                int gm = m0 + r;
                aR[it] = (gm < M)
                    ? *(const float4*)&g_T[(size_t)gm * 1024 + kn * 32 + c4 * 4]
                    : make_float4(0.f, 0.f, 0.f, 0.f);
            }
#pragma unroll
            for (int it = 0; it < 3; it++) {
                bhR[it] = ((const float4*)g_WBh)[kn * 768 + tid + 256 * it];
                blR[it] = ((const float4*)g_WBl)[kn * 768 + tid + 256 * it];
            }
        }

        // compute: 4 k8 steps
#pragma unroll
        for (int ks = 0; ks < 4; ks++) {
            int ab = (wid * 16 + (lane >> 2)) * APAD + ks * 8 + (lane & 3);
            uint32_t ah0 = __float_as_uint(Ahi[ab]);
            uint32_t ah1 = __float_as_uint(Ahi[ab + 8 * APAD]);
            uint32_t ah2 = __float_as_uint(Ahi[ab + 4]);
            uint32_t ah3 = __float_as_uint(Ahi[ab + 8 * APAD + 4]);
            uint32_t al0 = __float_as_uint(Alo[ab]);
            uint32_t al1 = __float_as_uint(Alo[ab + 8 * APAD]);
            uint32_t al2 = __float_as_uint(Alo[ab + 4]);
            uint32_t al3 = __float_as_uint(Alo[ab + 8 * APAD + 4]);
#pragma unroll
            for (int j = 0; j < 12; j++) {
                float2 bh = Bh[(ks * 12 + j) * 32 + lane];
                float2 bl = Bl[(ks * 12 + j) * 32 + lane];
                uint32_t bh0 = __float_as_uint(bh.x);
                uint32_t bh1 = __float_as_uint(bh.y);
                uint32_t bl0 = __float_as_uint(bl.x);
                uint32_t bl1 = __float_as_uint(bl.y);
                MMA_TF32(acc[j], ah0, ah1, ah2, ah3, bh0, bh1);
                MMA_TF32(acc[j], ah0, ah1, ah2, ah3, bl0, bl1);
                MMA_TF32(acc[j], al0, al1, al2, al3, bh0, bh1);
            }
        }
    }

    // epilogue
    int r = lane >> 2, c2 = (lane & 3) * 2;
    int gm0 = m0 + wid * 16 + r;
#pragma unroll
    for (int j = 0; j < 12; j++) {
        int col = j * 8 + c2;
        if (gm0 < M)
            *(float2*)&g_h[(size_t)gm0 * 96 + col] =
                make_float2(acc[j][0] * SCALE1, acc[j][1] * SCALE1);
        if (gm0 + 8 < M)
            *(float2*)&g_h[(size_t)(gm0 + 8) * 96 + col] =
                make_float2(acc[j][2] * SCALE1, acc[j][3] * SCALE1);
    }
}

// ---------------------------------------------------------------------------
// K8: per-node activation y, then z = W2b @ y
// ---------------------------------------------------------------------------
__global__ void __launch_bounds__(256) k_yz(const float* __restrict__ W2b, int N)
{
    __shared__ float sy[32][64];
    int n0 = blockIdx.x * 32;
    int tid = threadIdx.x;

    for (int q = tid; q < 2048; q += 256) {
        int node = q >> 6;
        int k = q & 63;
        int gn = n0 + node;
        float yv = 0.f;
        if (gn < N) {
            const float* hp = &g_h[(size_t)gn * 96];
            if (k < 32) {
                float s = hp[k];
                yv = (k < 16) ? fmaxf(s, 0.f) : fabsf(s);
            } else {
                int j = k - 32;
                float gv = hp[32 + j];
                float vv = hp[64 + j];
                float ga;
                if (j < 8)       ga = fmaxf(gv, 0.f);
                else if (j < 16) ga = tanhf(gv);
                else if (j < 24) ga = fmaxf(gv, 0.f);
                else             ga = tanhf(gv);
                yv = ga * vv;
            }
        }
        sy[node][k] = yv;
    }
    __syncthreads();

    int c = tid;
    float wreg[64];
#pragma unroll
    for (int k4 = 0; k4 < 16; k4++) {
        float4 v = *(const float4*)&W2b[c * 64 + k4 * 4];
        wreg[k4 * 4 + 0] = v.x; wreg[k4 * 4 + 1] = v.y;
        wreg[k4 * 4 + 2] = v.z; wreg[k4 * 4 + 3] = v.w;
    }
    for (int node = 0; node < 32; node++) {
        int gn = n0 + node;
        if (gn >= N) break;
        float s = 0.f;
#pragma unroll
        for (int k = 0; k < 64; k++) s = fmaf(wreg[k], sy[node][k], s);
        g_z[(size_t)gn * 256 + c] = s;
    }
}

// ---------------------------------------------------------------------------
// K9: final pass, warp per node over dst-sorted edges; no atomics
// ---------------------------------------------------------------------------
__global__ void __launch_bounds__(256) k_final(const float* __restrict__ W2a,
                                               const int* __restrict__ esrc,
                                               float* __restrict__ out, int N)
{
    __shared__ float sW[768];
    for (int i = threadIdx.x; i < 768; i += 256) sW[i] = W2a[i];
    __syncthreads();

    int w = blockIdx.x * 8 + (threadIdx.x >> 5);
    int lane = threadIdx.x & 31;
    if (w >= N) return;
    int beg = g_off[w], end = g_off[w + 1];

    float w0[8], w1[8], w2[8];
#pragma unroll
    for (int j = 0; j < 8; j++) {
        int c = j * 32 + lane;
        w0[j] = sW[c]; w1[j] = sW[256 + c]; w2[j] = sW[512 + c];
    }

    float sum = 0.f;
    for (int i = beg; i < end; i++) {
        int e = g_perm[i];
        int src = esrc[e];
        float4 bs = *(const float4*)&g_basis[(size_t)e * 4];
        const float* zp = &g_z[(size_t)src * 256];
#pragma unroll
        for (int j = 0; j < 8; j++) {
            int c = j * 32 + lane;
            float h2 = fmaxf(fmaf(bs.x, w0[j], fmaf(bs.y, w1[j], bs.z * w2[j])), 0.f);
            sum = fmaf(h2, zp[c], sum);
        }
    }
#pragma unroll
    for (int o = 16; o > 0; o >>= 1)
        sum += __shfl_down_sync(0xffffffffu, sum, o);
    if (lane == 0) out[w] = sum * SCALE2;
}

// ---------------------------------------------------------------------------
// Launch
// ---------------------------------------------------------------------------
extern "C" void kernel_launch(void* const* d_in, const int* in_sizes, int n_in,
                              void* d_out, int out_size)
{
    const float* edge_vec = (const float*)d_in[0];
    const float* edge_len = (const float*)d_in[1];
    const float* W1a      = (const float*)d_in[2];
    const float* W1b      = (const float*)d_in[3];
    const float* W2a      = (const float*)d_in[4];
    const float* W2b      = (const float*)d_in[5];
    const int*   esrc     = (const int*)d_in[6];
    const int*   edst     = (const int*)d_in[7];
    float* out = (float*)d_out;

    int E = in_sizes[1];
    int N = out_size;
    if (E > EMAX) E = EMAX;
    if (N > NMAX) N = NMAX;

    cudaFuncSetAttribute(k_gemm_mma,
                         cudaFuncAttributeMaxDynamicSharedMemorySize, GM_SMEM);

    k_zero<<<(N + 255) / 256, 256>>>(N);
    k_sh<<<(E + 255) / 256, 256>>>(edge_vec, edst, E);
    k_reord<<<(49152 + 255) / 256, 256>>>(W1b);
    k_scan<<<1, 1024>>>(E, N);
    k_place<<<(E + 255) / 256, 256>>>(edst, E);
    k_x<<<(N + 15) / 16, 256>>>(N);
    k_dotsb<<<(E + 255) / 256, 256>>>(edge_len, esrc, E);
    k_buildT<<<(N + 7) / 8, 256>>>(W1a, N);
    k_gemm_mma<<<(N + 127) / 128, 256, GM_SMEM>>>(N);
    k_yz<<<(N + 31) / 32, 256>>>(W2b, N);
    k_final<<<(N + 7) / 8, 256>>>(W2a, esrc, out, N);
}

// round 5
// speedup vs baseline: 1.4749x; 1.3460x over previous
#include <cuda_runtime.h>
#include <cuda_bf16.h>
#include <math.h>
#include <stdint.h>

#define EMAX 250000
#define NMAX 25000

#define INV_NN   0.51298917604257706f   // 1/sqrt(3.8)
#define INV3     0.57735026918962576f
#define INV112   0.89285714285714285f   // 1/1.12
#define S3       1.7320508075688772f
#define S5       2.2360679774997896f
#define S7       2.6457513110645907f
#define S15      3.8729833462074170f
#define S105     10.246950765959598f
#define C358     2.0916500663351889f
#define C218     1.6201851746019651f
#define RS3      0.57735026918962576f
#define RS5      0.44721359549995794f
#define RS7      0.37796447300922720f
#define SCALE1   (INV3 * 0.5f / 16.0f * INV_NN)
#define SCALE2   (INV3 / 128.0f * INV_NN)

// ---------------------------------------------------------------------------
// Scratch
// ---------------------------------------------------------------------------
__device__ __align__(16) float g_sh   [EMAX * 16];
__device__ __align__(16) float g_x    [NMAX * 16];
__device__ __align__(16) float g_dots [EMAX * 4];
__device__ __align__(16) float g_basis[EMAX * 4];
__device__ int   g_hist[NMAX];
__device__ int   g_off [NMAX + 1];
__device__ int   g_cur [NMAX];
__device__ int   g_perm[EMAX];
// T split into two bf16 planes, row = 512 uint32 words (1024 bf16)
__device__ __align__(16) uint32_t g_T1 [(size_t)NMAX * 512];
__device__ __align__(16) uint32_t g_T2 [(size_t)NMAX * 512];
// W1b in m16n8k16 fragment order: uint4 {B1b0,B1b1,B2b0,B2b1}
//   idx = ((kc*2+ks)*12 + j)*32 + lane, count = 32*2*12*32 = 24576
__device__ __align__(16) uint4 g_WB [24576];
__device__ __align__(16) float g_h   [NMAX * 96];
__device__ __align__(16) float g_z   [(size_t)NMAX * 256];

// ---------------------------------------------------------------------------
// helpers
// ---------------------------------------------------------------------------
#define MMA_BF16(d, a0, a1, a2, a3, b0, b1)                                   \
    asm volatile("mma.sync.aligned.m16n8k16.row.col.f32.bf16.bf16.f32 "       \
        "{%0,%1,%2,%3},{%4,%5,%6,%7},{%8,%9},{%0,%1,%2,%3};"                  \
        : "+f"((d)[0]), "+f"((d)[1]), "+f"((d)[2]), "+f"((d)[3])              \
        : "r"(a0), "r"(a1), "r"(a2), "r"(a3), "r"(b0), "r"(b1))

__device__ __forceinline__ uint32_t pack_bf2(float a, float b) {
    __nv_bfloat162 t = __floats2bfloat162_rn(a, b);
    return *(uint32_t*)&t;
}
__device__ __forceinline__ float bf_round(float v) {
    __nv_bfloat16 t = __float2bfloat16_rn(v);
    return __bfloat162float(t);
}

// ---------------------------------------------------------------------------
// K0: zero histogram
// ---------------------------------------------------------------------------
__global__ void k_zero(int N)
{
    int i = blockIdx.x * blockDim.x + threadIdx.x;
    if (i < N) g_hist[i] = 0;
}

// ---------------------------------------------------------------------------
// K1: spherical harmonics per edge + dst histogram
// ---------------------------------------------------------------------------
__global__ void k_sh(const float* __restrict__ edge_vec,
                     const int*   __restrict__ edst, int E)
{
    int e = blockIdx.x * blockDim.x + threadIdx.x;
    if (e >= E) return;
    float x = edge_vec[e * 3 + 0];
    float y = edge_vec[e * 3 + 1];
    float z = edge_vec[e * 3 + 2];
    float inv = 1.0f / (sqrtf(x * x + y * y + z * z) + 1e-12f);
    x *= inv; y *= inv; z *= inv;
    float x2 = x * x, y2 = y * y, z2 = z * z;

    float4* shp = (float4*)&g_sh[(size_t)e * 16];
    shp[0] = make_float4(1.0f, S3 * x, S3 * y, S3 * z);
    shp[1] = make_float4(S15 * x * z, S15 * x * y,
                         0.5f * S5 * (2.0f * y2 - x2 - z2), S15 * y * z);
    shp[2] = make_float4(0.5f * S15 * (z2 - x2),
                         C358 * x * (3.0f * z2 - x2),
                         S105 * x * y * z,
                         C218 * x * (4.0f * y2 - z2 - x2));
    shp[3] = make_float4(0.5f * S7 * y * (2.0f * y2 - 3.0f * z2 - 3.0f * x2),
                         C218 * z * (4.0f * y2 - z2 - x2),
                         0.5f * S105 * y * (z2 - x2),
                         C358 * z * (z2 - 3.0f * x2));

    atomicAdd(&g_hist[edst[e]], 1);
}

// ---------------------------------------------------------------------------
// K2: exclusive scan via smem transpose (one block, ~4 syncs)
// ---------------------------------------------------------------------------
__global__ void __launch_bounds__(1024) k_scan(int E, int N)
{
    extern __shared__ int s[];
    int t = threadIdx.x, lane = t & 31, wid = t >> 5;
    for (int i = t; i < N; i += 1024) s[i] = g_hist[i];
    __syncthreads();

    const int C = 25;
    int base = t * C;
    int loc[C];
    int tot = 0;
#pragma unroll
    for (int i = 0; i < C; i++) {
        int idx = base + i;
        int v = (idx < N) ? s[idx] : 0;
        loc[i] = tot; tot += v;
    }
    __shared__ int wsum[32];
    __shared__ int wpre[32];
    int xv = tot;
#pragma unroll
    for (int o = 1; o < 32; o <<= 1) {
        int tt = __shfl_up_sync(0xffffffffu, xv, o);
        if (lane >= o) xv += tt;
    }
    if (lane == 31) wsum[wid] = xv;
    __syncthreads();
    if (wid == 0) {
        int wv = wsum[lane];
        int xs = wv;
#pragma unroll
        for (int o = 1; o < 32; o <<= 1) {
            int tt = __shfl_up_sync(0xffffffffu, xs, o);
            if (lane >= o) xs += tt;
        }
        wpre[lane] = xs - wv;
    }
    __syncthreads();
    int texcl = (xv - tot) + wpre[wid];
#pragma unroll
    for (int i = 0; i < C; i++) {
        int idx = base + i;
        if (idx < N) s[idx] = texcl + loc[i];
    }
    __syncthreads();
    for (int i = t; i < N; i += 1024) {
        int v = s[i];
        g_off[i] = v; g_cur[i] = v;
    }
    if (t == 0) g_off[N] = E;
}

// ---------------------------------------------------------------------------
// K3: counting-sort placement
// ---------------------------------------------------------------------------
__global__ void k_place(const int* __restrict__ edst, int E)
{
    int e = blockIdx.x * blockDim.x + threadIdx.x;
    if (e >= E) return;
    int pos = atomicAdd(&g_cur[edst[e]], 1);
    g_perm[pos] = e;
}

// ---------------------------------------------------------------------------
// K4: x[n,c] gather-sum
// ---------------------------------------------------------------------------
__global__ void __launch_bounds__(256) k_x(int N)
{
    int n = blockIdx.x * 16 + (threadIdx.x >> 4);
    int c = threadIdx.x & 15;
    if (n >= N) return;
    int beg = g_off[n], end = g_off[n + 1];
    float acc = 0.f;
    for (int i = beg; i < end; i++) {
        int e = g_perm[i];
        acc += g_sh[(size_t)e * 16 + c];
    }
    g_x[n * 16 + c] = acc;
}

// ---------------------------------------------------------------------------
// K2b: W1b -> bf16 hi/lo split in m16n8k16 B-fragment order
//   b0 elems: k = kbase, kbase+1 ; b1: kbase+8, kbase+9 ; n = j*8 + lane/4
// ---------------------------------------------------------------------------
__global__ void k_reord(const float* __restrict__ W1b)
{
    int idx = blockIdx.x * blockDim.x + threadIdx.x;
    if (idx >= 24576) return;
    int lane = idx & 31;
    int t = idx >> 5;          // 0..767
    int j = t % 12;
    int t2 = t / 12;           // 0..63  = kc*2+ks
    int n = j * 8 + (lane >> 2);
    int kbase = t2 * 16 + (lane & 3) * 2;

    float v[4], h[4], l[4];
    int kks[4] = {kbase, kbase + 1, kbase + 8, kbase + 9};
#pragma unroll
    for (int q = 0; q < 4; q++) {
        int kk = kks[q];
        int c = kk >> 2, p = kk & 3;
        v[q] = W1b[c * 384 + p * 96 + n];
        h[q] = bf_round(v[q]);
        l[q] = v[q] - h[q];
    }
    uint4 o;
    o.x = pack_bf2(h[0], h[1]);
    o.y = pack_bf2(h[2], h[3]);
    o.z = pack_bf2(l[0], l[1]);
    o.w = pack_bf2(l[2], l[3]);
    g_WB[idx] = o;
}

// ---------------------------------------------------------------------------
// K5: per-edge dots + radial basis
// ---------------------------------------------------------------------------
__global__ void k_dotsb(const float* __restrict__ edge_len,
                        const int*  __restrict__ esrc, int E)
{
    int e = blockIdx.x * blockDim.x + threadIdx.x;
    if (e >= E) return;
    int src = esrc[e];
    const float4* shp = (const float4*)&g_sh[(size_t)e * 16];
    const float4* xp  = (const float4*)&g_x[(size_t)src * 16];
    float4 s0 = shp[0], s1 = shp[1], s2 = shp[2], s3 = shp[3];
    float4 x0 = xp[0],  x1 = xp[1],  x2 = xp[2],  x3 = xp[3];

    float d0 = x0.x * s0.x;
    float d1 = (x0.y * s0.y + x0.z * s0.z + x0.w * s0.w) * RS3;
    float d2 = (x1.x * s1.x + x1.y * s1.y + x1.z * s1.z + x1.w * s1.w + x2.x * s2.x) * RS5;
    float d3 = (x2.y * s2.y + x2.z * s2.z + x2.w * s2.w +
                x3.x * s3.x + x3.y * s3.y + x3.z * s3.z + x3.w * s3.w) * RS7;
    *(float4*)&g_dots[(size_t)e * 4] =
        make_float4(d0 * INV_NN, d1 * INV_NN, d2 * INV_NN, d3 * INV_NN);

    float len = edge_len[e];
    float t0 = len * 0.5f;
    float t1 = (len - 2.0f) * 0.5f;
    float t2 = (len - 4.0f) * 0.5f;
    *(float4*)&g_basis[(size_t)e * 4] =
        make_float4(expf(-t0 * t0) * INV112, expf(-t1 * t1) * INV112,
                    expf(-t2 * t2) * INV112, 0.f);
}

// ---------------------------------------------------------------------------
// K6: build T[n, c*4+p]; one warp per node; store bf16 hi/lo planes
// ---------------------------------------------------------------------------
__global__ void __launch_bounds__(256) k_buildT(const float* __restrict__ W1a, int N)
{
    __shared__ float sW[768];
    for (int i = threadIdx.x; i < 768; i += 256) sW[i] = W1a[i];
    __syncthreads();

    int w = blockIdx.x * 8 + (threadIdx.x >> 5);
    int lane = threadIdx.x & 31;
    if (w >= N) return;
    int beg = g_off[w], end = g_off[w + 1];

    float wa0[8], wa1[8], wa2[8];
#pragma unroll
    for (int j = 0; j < 8; j++) {
        int c = j * 32 + lane;
        wa0[j] = sW[c]; wa1[j] = sW[256 + c]; wa2[j] = sW[512 + c];
    }
    float4 acc[8];
#pragma unroll
    for (int j = 0; j < 8; j++) acc[j] = make_float4(0.f, 0.f, 0.f, 0.f);

    for (int i = beg; i < end; i++) {
        int e = g_perm[i];
        float4 bs = *(const float4*)&g_basis[(size_t)e * 4];
        float4 dt = *(const float4*)&g_dots[(size_t)e * 4];
#pragma unroll
        for (int j = 0; j < 8; j++) {
            float h1 = fmaxf(fmaf(bs.x, wa0[j], fmaf(bs.y, wa1[j], bs.z * wa2[j])), 0.f);
            acc[j].x = fmaf(h1, dt.x, acc[j].x);
            acc[j].y = fmaf(h1, dt.y, acc[j].y);
            acc[j].z = fmaf(h1, dt.z, acc[j].z);
            acc[j].w = fmaf(h1, dt.w, acc[j].w);
        }
    }
    uint32_t* t1 = &g_T1[(size_t)w * 512];
    uint32_t* t2 = &g_T2[(size_t)w * 512];
#pragma unroll
    for (int j = 0; j < 8; j++) {
        int idx = j * 32 + lane;         // 4 bf16 elements each
        float4 v = acc[j];
        float hx = bf_round(v.x), hy = bf_round(v.y);
        float hz = bf_round(v.z), hw = bf_round(v.w);
        uint2 w1 = make_uint2(pack_bf2(hx, hy), pack_bf2(hz, hw));
        uint2 w2 = make_uint2(pack_bf2(v.x - hx, v.y - hy),
                              pack_bf2(v.z - hz, v.w - hw));
        *(uint2*)&t1[idx * 2] = w1;
        *(uint2*)&t2[idx * 2] = w2;
    }
}

// ---------------------------------------------------------------------------
// K7: node GEMM h = T @ W^T * SCALE1 via 3xBF16 mma.sync (m16n8k16)
//     CTA: 256 thr (8 warps), tile M=128 x N=96, BK=32 (16 words per row)
// ---------------------------------------------------------------------------
#define ASTR 20   // words per smem A row (16 used + 4 pad; 80B, 16B aligned)

__global__ void __launch_bounds__(256) k_gemm_bf16(int M)
{
    __shared__ uint32_t A1s[128 * ASTR];
    __shared__ uint32_t A2s[128 * ASTR];
    __shared__ uint4    Bs[768];

    int tid = threadIdx.x, wid = tid >> 5, lane = tid & 31;
    int m0 = blockIdx.x * 128;

    float acc[12][4];
#pragma unroll
    for (int j = 0; j < 12; j++)
#pragma unroll
        for (int q = 0; q < 4; q++) acc[j][q] = 0.f;

    uint4 a1R[2], a2R[2], bR[3];
    const uint4 zero4 = make_uint4(0u, 0u, 0u, 0u);

    // prefetch kc=0
#pragma unroll
    for (int it = 0; it < 2; it++) {
        int idx = tid + 256 * it;
        int r = idx >> 2, qc = idx & 3;
        int gm = m0 + r;
        if (gm < M) {
            a1R[it] = *(const uint4*)&g_T1[(size_t)gm * 512 + qc * 4];
            a2R[it] = *(const uint4*)&g_T2[(size_t)gm * 512 + qc * 4];
        } else { a1R[it] = zero4; a2R[it] = zero4; }
    }
#pragma unroll
    for (int it = 0; it < 3; it++)
        bR[it] = g_WB[tid + 256 * it];

    for (int kc = 0; kc < 32; kc++) {
        __syncthreads();
#pragma unroll
        for (int it = 0; it < 2; it++) {
            int idx = tid + 256 * it;
            int r = idx >> 2, qc = idx & 3;
            *(uint4*)&A1s[r * ASTR + qc * 4] = a1R[it];
            *(uint4*)&A2s[r * ASTR + qc * 4] = a2R[it];
        }
#pragma unroll
        for (int it = 0; it < 3; it++)
            Bs[tid + 256 * it] = bR[it];
        __syncthreads();

        if (kc < 31) {
            int kn = kc + 1;
#pragma unroll
            for (int it = 0; it < 2; it++) {
                int idx = tid + 256 * it;
                int r = idx >> 2, qc = idx & 3;
                int gm = m0 + r;
                if (gm < M) {
                    a1R[it] = *(const uint4*)&g_T1[(size_t)gm * 512 + kn * 16 + qc * 4];
                    a2R[it] = *(const uint4*)&g_T2[(size_t)gm * 512 + kn * 16 + qc * 4];
                } else { a1R[it] = zero4; a2R[it] = zero4; }
            }
#pragma unroll
            for (int it = 0; it < 3; it++)
                bR[it] = g_WB[kn * 768 + tid + 256 * it];
        }

#pragma unroll
        for (int ks = 0; ks < 2; ks++) {
            int ar = (wid * 16 + (lane >> 2)) * ASTR + ks * 8 + (lane & 3);
            uint32_t a10 = A1s[ar];
            uint32_t a11 = A1s[ar + 8 * ASTR];
            uint32_t a12 = A1s[ar + 4];
            uint32_t a13 = A1s[ar + 8 * ASTR + 4];
            uint32_t a20 = A2s[ar];
            uint32_t a21 = A2s[ar + 8 * ASTR];
            uint32_t a22 = A2s[ar + 4];
            uint32_t a23 = A2s[ar + 8 * ASTR + 4];
#pragma unroll
            for (int j = 0; j < 12; j++) {
                uint4 b = Bs[(ks * 12 + j) * 32 + lane];
                MMA_BF16(acc[j], a10, a11, a12, a13, b.x, b.y);
                MMA_BF16(acc[j], a10, a11, a12, a13, b.z, b.w);
                MMA_BF16(acc[j], a20, a21, a22, a23, b.x, b.y);
            }
        }
    }

    // epilogue (D fragment: c0,c1 row=lane/4 col=(lane&3)*2; c2,c3 row+8)
    int r = lane >> 2, c2 = (lane & 3) * 2;
    int gm0 = m0 + wid * 16 + r;
#pragma unroll
    for (int j = 0; j < 12; j++) {
        int col = j * 8 + c2;
        if (gm0 < M)
            *(float2*)&g_h[(size_t)gm0 * 96 + col] =
                make_float2(acc[j][0] * SCALE1, acc[j][1] * SCALE1);
        if (gm0 + 8 < M)
            *(float2*)&g_h[(size_t)(gm0 + 8) * 96 + col] =
                make_float2(acc[j][2] * SCALE1, acc[j][3] * SCALE1);
    }
}

// ---------------------------------------------------------------------------
// K8: per-node activation y, then z = W2b @ y
// ---------------------------------------------------------------------------
__global__ void __launch_bounds__(256) k_yz(const float* __restrict__ W2b, int N)
{
    __shared__ float sy[32][64];
    int n0 = blockIdx.x * 32;
    int tid = threadIdx.x;

    for (int q = tid; q < 2048; q += 256) {
        int node = q >> 6;
        int k = q & 63;
        int gn = n0 + node;
        float yv = 0.f;
        if (gn < N) {
            const float* hp = &g_h[(size_t)gn * 96];
            if (k < 32) {
                float s = hp[k];
                yv = (k < 16) ? fmaxf(s, 0.f) : fabsf(s);
            } else {
                int j = k - 32;
                float gv = hp[32 + j];
                float vv = hp[64 + j];
                float ga;
                if (j < 8)       ga = fmaxf(gv, 0.f);
                else if (j < 16) ga = tanhf(gv);
                else if (j < 24) ga = fmaxf(gv, 0.f);
                else             ga = tanhf(gv);
                yv = ga * vv;
            }
        }
        sy[node][k] = yv;
    }
    __syncthreads();

    int c = tid;
    float wreg[64];
#pragma unroll
    for (int k4 = 0; k4 < 16; k4++) {
        float4 v = *(const float4*)&W2b[c * 64 + k4 * 4];
        wreg[k4 * 4 + 0] = v.x; wreg[k4 * 4 + 1] = v.y;
        wreg[k4 * 4 + 2] = v.z; wreg[k4 * 4 + 3] = v.w;
    }
    for (int node = 0; node < 32; node++) {
        int gn = n0 + node;
        if (gn >= N) break;
        float s = 0.f;
#pragma unroll
        for (int k = 0; k < 64; k++) s = fmaf(wreg[k], sy[node][k], s);
        g_z[(size_t)gn * 256 + c] = s;
    }
}

// ---------------------------------------------------------------------------
// K9: final pass, warp per node over dst-sorted edges; no atomics
// ---------------------------------------------------------------------------
__global__ void __launch_bounds__(256) k_final(const float* __restrict__ W2a,
                                               const int* __restrict__ esrc,
                                               float* __restrict__ out, int N)
{
    __shared__ float sW[768];
    for (int i = threadIdx.x; i < 768; i += 256) sW[i] = W2a[i];
    __syncthreads();

    int w = blockIdx.x * 8 + (threadIdx.x >> 5);
    int lane = threadIdx.x & 31;
    if (w >= N) return;
    int beg = g_off[w], end = g_off[w + 1];

    float w0[8], w1[8], w2[8];
#pragma unroll
    for (int j = 0; j < 8; j++) {
        int c = j * 32 + lane;
        w0[j] = sW[c]; w1[j] = sW[256 + c]; w2[j] = sW[512 + c];
    }

    float sum = 0.f;
    for (int i = beg; i < end; i++) {
        int e = g_perm[i];
        int src = esrc[e];
        float4 bs = *(const float4*)&g_basis[(size_t)e * 4];
        const float* zp = &g_z[(size_t)src * 256];
#pragma unroll
        for (int j = 0; j < 8; j++) {
            int c = j * 32 + lane;
            float h2 = fmaxf(fmaf(bs.x, w0[j], fmaf(bs.y, w1[j], bs.z * w2[j])), 0.f);
            sum = fmaf(h2, zp[c], sum);
        }
    }
#pragma unroll
    for (int o = 16; o > 0; o >>= 1)
        sum += __shfl_down_sync(0xffffffffu, sum, o);
    if (lane == 0) out[w] = sum * SCALE2;
}

// ---------------------------------------------------------------------------
// Launch
// ---------------------------------------------------------------------------
extern "C" void kernel_launch(void* const* d_in, const int* in_sizes, int n_in,
                              void* d_out, int out_size)
{
    const float* edge_vec = (const float*)d_in[0];
    const float* edge_len = (const float*)d_in[1];
    const float* W1a      = (const float*)d_in[2];
    const float* W1b      = (const float*)d_in[3];
    const float* W2a      = (const float*)d_in[4];
    const float* W2b      = (const float*)d_in[5];
    const int*   esrc     = (const int*)d_in[6];
    const int*   edst     = (const int*)d_in[7];
    float* out = (float*)d_out;

    int E = in_sizes[1];
    int N = out_size;
    if (E > EMAX) E = EMAX;
    if (N > NMAX) N = NMAX;

    int scan_smem = (N + 24) * 4;
    cudaFuncSetAttribute(k_scan,
                         cudaFuncAttributeMaxDynamicSharedMemorySize, 102400);

    k_zero<<<(N + 255) / 256, 256>>>(N);
    k_sh<<<(E + 255) / 256, 256>>>(edge_vec, edst, E);
    k_reord<<<(24576 + 255) / 256, 256>>>(W1b);
    k_scan<<<1, 1024, scan_smem>>>(E, N);
    k_place<<<(E + 255) / 256, 256>>>(edst, E);
    k_x<<<(N + 15) / 16, 256>>>(N);
    k_dotsb<<<(E + 255) / 256, 256>>>(edge_len, esrc, E);
    k_buildT<<<(N + 7) / 8, 256>>>(W1a, N);
    k_gemm_bf16<<<(N + 127) / 128, 256>>>(N);
    k_yz<<<(N + 31) / 32, 256>>>(W2b, N);
    k_final<<<(N + 7) / 8, 256>>>(W2a, esrc, out, N);
}

// round 6
// speedup vs baseline: 1.8672x; 1.2660x over previous
#include <cuda_runtime.h>
#include <cuda_bf16.h>
#include <math.h>
#include <stdint.h>

#define EMAX 250000
#define NMAX 25000

#define INV_NN   0.51298917604257706f   // 1/sqrt(3.8)
#define INV3     0.57735026918962576f
#define INV112   0.89285714285714285f   // 1/1.12
#define S3       1.7320508075688772f
#define S5       2.2360679774997896f
#define S7       2.6457513110645907f
#define S15      3.8729833462074170f
#define S105     10.246950765959598f
#define C358     2.0916500663351889f
#define C218     1.6201851746019651f
#define RS3      0.57735026918962576f
#define RS5      0.44721359549995794f
#define RS7      0.37796447300922720f
#define SCALE1   (INV3 * 0.5f / 16.0f * INV_NN)
#define SCALE2   (INV3 / 128.0f * INV_NN)

// ---------------------------------------------------------------------------
// Scratch (all dst-sorted arrays carry suffix S)
// ---------------------------------------------------------------------------
__device__ __align__(16) float g_shS   [EMAX * 16];
__device__ __align__(16) float g_x     [NMAX * 16];
__device__ __align__(16) float g_dotsS [EMAX * 4];
__device__ __align__(16) float g_basisS[EMAX * 4];
__device__ int   g_hist[NMAX];
__device__ int   g_off [NMAX + 1];
__device__ int   g_cur [NMAX];
__device__ int   g_bsum[32];
__device__ int   g_pos [EMAX];
__device__ int   g_srcS[EMAX];
__device__ __align__(16) uint32_t g_T1 [(size_t)NMAX * 512];
__device__ __align__(16) uint32_t g_T2 [(size_t)NMAX * 512];
__device__ __align__(16) uint4 g_WB  [24576];  // W1b frag-ordered hi/lo
__device__ __align__(16) uint4 g_WB2 [4096];   // W2b frag-ordered hi/lo
__device__ __align__(16) float g_h   [NMAX * 96];
__device__ __align__(16) float g_z   [(size_t)NMAX * 256];

// ---------------------------------------------------------------------------
// helpers
// ---------------------------------------------------------------------------
#define MMA_BF16(d, a0, a1, a2, a3, b0, b1)                                   \
    asm volatile("mma.sync.aligned.m16n8k16.row.col.f32.bf16.bf16.f32 "       \
        "{%0,%1,%2,%3},{%4,%5,%6,%7},{%8,%9},{%0,%1,%2,%3};"                  \
        : "+f"((d)[0]), "+f"((d)[1]), "+f"((d)[2]), "+f"((d)[3])              \
        : "r"(a0), "r"(a1), "r"(a2), "r"(a3), "r"(b0), "r"(b1))

__device__ __forceinline__ uint32_t pack_bf2(float a, float b) {
    __nv_bfloat162 t = __floats2bfloat162_rn(a, b);
    return *(uint32_t*)&t;
}
__device__ __forceinline__ float bf_round(float v) {
    __nv_bfloat16 t = __float2bfloat16_rn(v);
    return __bfloat162float(t);
}

// ---------------------------------------------------------------------------
// K0: zero histogram
// ---------------------------------------------------------------------------
__global__ void k_zero(int N)
{
    int i = blockIdx.x * blockDim.x + threadIdx.x;
    if (i < N) g_hist[i] = 0;
}

// K1: dst histogram
__global__ void k_hist(const int* __restrict__ edst, int E)
{
    int e = blockIdx.x * blockDim.x + threadIdx.x;
    if (e < E) atomicAdd(&g_hist[edst[e]], 1);
}

// ---------------------------------------------------------------------------
// K2a/K2b: two-phase multi-block exclusive scan
// ---------------------------------------------------------------------------
__global__ void __launch_bounds__(1024) k_scanA(int N)
{
    int b = blockIdx.x, t = threadIdx.x;
    int lane = t & 31, wid = t >> 5;
    int idx = b * 1024 + t;
    int v = (idx < N) ? g_hist[idx] : 0;
    int xv = v;
#pragma unroll
    for (int o = 1; o < 32; o <<= 1) {
        int tt = __shfl_up_sync(0xffffffffu, xv, o);
        if (lane >= o) xv += tt;
    }
    __shared__ int wsum[32];
    __shared__ int wpre[32];
    if (lane == 31) wsum[wid] = xv;
    __syncthreads();
    if (wid == 0) {
        int wv = wsum[lane];
        int xs = wv;
#pragma unroll
        for (int o = 1; o < 32; o <<= 1) {
            int tt = __shfl_up_sync(0xffffffffu, xs, o);
            if (lane >= o) xs += tt;
        }
        wpre[lane] = xs - wv;
    }
    __syncthreads();
    int incl = xv + wpre[wid];
    if (idx < N) g_off[idx] = incl - v;   // local exclusive
    if (t == 1023) g_bsum[b] = incl;      // block total
}

__global__ void __launch_bounds__(1024) k_scanB(int E, int N)
{
    int b = blockIdx.x, t = threadIdx.x;
    int idx = b * 1024 + t;
    __shared__ int spre;
    if (t < 32) {
        int v = (t < b) ? g_bsum[t] : 0;
#pragma unroll
        for (int o = 16; o > 0; o >>= 1)
            v += __shfl_down_sync(0xffffffffu, v, o);
        if (t == 0) spre = v;
    }
    __syncthreads();
    if (idx < N) {
        int val = g_off[idx] + spre;
        g_off[idx] = val;
        g_cur[idx] = val;
    }
    if (idx == N) g_off[N] = E;
}

// ---------------------------------------------------------------------------
// K3: placement + basis (sorted writes)
// ---------------------------------------------------------------------------
__global__ void k_place(const int*   __restrict__ edst,
                        const int*   __restrict__ esrc,
                        const float* __restrict__ edge_len, int E)
{
    int e = blockIdx.x * blockDim.x + threadIdx.x;
    if (e >= E) return;
    int pos = atomicAdd(&g_cur[edst[e]], 1);
    g_pos[e] = pos;
    g_srcS[pos] = esrc[e];
    float len = edge_len[e];
    float t0 = len * 0.5f;
    float t1 = (len - 2.0f) * 0.5f;
    float t2 = (len - 4.0f) * 0.5f;
    *(float4*)&g_basisS[(size_t)pos * 4] =
        make_float4(expf(-t0 * t0) * INV112, expf(-t1 * t1) * INV112,
                    expf(-t2 * t2) * INV112, 0.f);
}

// ---------------------------------------------------------------------------
// K4: spherical harmonics, written to sorted slot
// ---------------------------------------------------------------------------
__global__ void k_sh(const float* __restrict__ edge_vec, int E)
{
    int e = blockIdx.x * blockDim.x + threadIdx.x;
    if (e >= E) return;
    float x = edge_vec[e * 3 + 0];
    float y = edge_vec[e * 3 + 1];
    float z = edge_vec[e * 3 + 2];
    float inv = 1.0f / (sqrtf(x * x + y * y + z * z) + 1e-12f);
    x *= inv; y *= inv; z *= inv;
    float x2 = x * x, y2 = y * y, z2 = z * z;

    int pos = g_pos[e];
    float4* shp = (float4*)&g_shS[(size_t)pos * 16];
    shp[0] = make_float4(1.0f, S3 * x, S3 * y, S3 * z);
    shp[1] = make_float4(S15 * x * z, S15 * x * y,
                         0.5f * S5 * (2.0f * y2 - x2 - z2), S15 * y * z);
    shp[2] = make_float4(0.5f * S15 * (z2 - x2),
                         C358 * x * (3.0f * z2 - x2),
                         S105 * x * y * z,
                         C218 * x * (4.0f * y2 - z2 - x2));
    shp[3] = make_float4(0.5f * S7 * y * (2.0f * y2 - 3.0f * z2 - 3.0f * x2),
                         C218 * z * (4.0f * y2 - z2 - x2),
                         0.5f * S105 * y * (z2 - x2),
                         C358 * z * (z2 - 3.0f * x2));
}

// ---------------------------------------------------------------------------
// K5: x[n,c] gather-sum over contiguous sorted sh
// ---------------------------------------------------------------------------
__global__ void __launch_bounds__(256) k_x(int N)
{
    int n = blockIdx.x * 16 + (threadIdx.x >> 4);
    int c = threadIdx.x & 15;
    if (n >= N) return;
    int beg = g_off[n], end = g_off[n + 1];
    float acc = 0.f;
    for (int i = beg; i < end; i++)
        acc += g_shS[(size_t)i * 16 + c];
    g_x[n * 16 + c] = acc;
}

// ---------------------------------------------------------------------------
// K6: W1b -> bf16 hi/lo frag order (m16n8k16)
// ---------------------------------------------------------------------------
__global__ void k_reord(const float* __restrict__ W1b)
{
    int idx = blockIdx.x * blockDim.x + threadIdx.x;
    if (idx >= 24576) return;
    int lane = idx & 31;
    int t = idx >> 5;
    int j = t % 12;
    int t2 = t / 12;
    int n = j * 8 + (lane >> 2);
    int kbase = t2 * 16 + (lane & 3) * 2;

    float v[4], h[4];
    int kks[4] = {kbase, kbase + 1, kbase + 8, kbase + 9};
#pragma unroll
    for (int q = 0; q < 4; q++) {
        int kk = kks[q];
        int c = kk >> 2, p = kk & 3;
        v[q] = W1b[c * 384 + p * 96 + n];
        h[q] = bf_round(v[q]);
    }
    uint4 o;
    o.x = pack_bf2(h[0], h[1]);
    o.y = pack_bf2(h[2], h[3]);
    o.z = pack_bf2(v[0] - h[0], v[1] - h[1]);
    o.w = pack_bf2(v[2] - h[2], v[3] - h[3]);
    g_WB[idx] = o;
}

// K6b: W2b -> bf16 hi/lo frag order
__global__ void k_reord2(const float* __restrict__ W2b)
{
    int idx = blockIdx.x * blockDim.x + threadIdx.x;
    if (idx >= 4096) return;
    int lane = idx & 31;
    int t = idx >> 5;       // 0..127
    int ks = t & 3;
    int j  = t >> 2;        // 0..31
    int n = j * 8 + (lane >> 2);
    int k0 = ks * 16 + (lane & 3) * 2;
    float v00 = W2b[n * 64 + k0],     v01 = W2b[n * 64 + k0 + 1];
    float v10 = W2b[n * 64 + k0 + 8], v11 = W2b[n * 64 + k0 + 9];
    float h00 = bf_round(v00), h01 = bf_round(v01);
    float h10 = bf_round(v10), h11 = bf_round(v11);
    uint4 o;
    o.x = pack_bf2(h00, h01);
    o.y = pack_bf2(h10, h11);
    o.z = pack_bf2(v00 - h00, v01 - h01);
    o.w = pack_bf2(v10 - h10, v11 - h11);
    g_WB2[idx] = o;
}

// ---------------------------------------------------------------------------
// K7: per-edge dots (sorted in & out)
// ---------------------------------------------------------------------------
__global__ void k_dotsb(int E)
{
    int i = blockIdx.x * blockDim.x + threadIdx.x;
    if (i >= E) return;
    int src = g_srcS[i];
    const float4* shp = (const float4*)&g_shS[(size_t)i * 16];
    const float4* xp  = (const float4*)&g_x[(size_t)src * 16];
    float4 s0 = shp[0], s1 = shp[1], s2 = shp[2], s3 = shp[3];
    float4 x0 = xp[0],  x1 = xp[1],  x2 = xp[2],  x3 = xp[3];

    float d0 = x0.x * s0.x;
    float d1 = (x0.y * s0.y + x0.z * s0.z + x0.w * s0.w) * RS3;
    float d2 = (x1.x * s1.x + x1.y * s1.y + x1.z * s1.z + x1.w * s1.w + x2.x * s2.x) * RS5;
    float d3 = (x2.y * s2.y + x2.z * s2.z + x2.w * s2.w +
                x3.x * s3.x + x3.y * s3.y + x3.z * s3.z + x3.w * s3.w) * RS7;
    *(float4*)&g_dotsS[(size_t)i * 4] =
        make_float4(d0 * INV_NN, d1 * INV_NN, d2 * INV_NN, d3 * INV_NN);
}

// ---------------------------------------------------------------------------
// K8: build T (streaming reads); store bf16 hi/lo planes
// ---------------------------------------------------------------------------
__global__ void __launch_bounds__(256) k_buildT(const float* __restrict__ W1a, int N)
{
    __shared__ float sW[768];
    for (int i = threadIdx.x; i < 768; i += 256) sW[i] = W1a[i];
    __syncthreads();

    int w = blockIdx.x * 8 + (threadIdx.x >> 5);
    int lane = threadIdx.x & 31;
    if (w >= N) return;
    int beg = g_off[w], end = g_off[w + 1];

    float wa0[8], wa1[8], wa2[8];
#pragma unroll
    for (int j = 0; j < 8; j++) {
        int c = j * 32 + lane;
        wa0[j] = sW[c]; wa1[j] = sW[256 + c]; wa2[j] = sW[512 + c];
    }
    float4 acc[8];
#pragma unroll
    for (int j = 0; j < 8; j++) acc[j] = make_float4(0.f, 0.f, 0.f, 0.f);

    for (int i = beg; i < end; i++) {
        float4 bs = *(const float4*)&g_basisS[(size_t)i * 4];
        float4 dt = *(const float4*)&g_dotsS[(size_t)i * 4];
#pragma unroll
        for (int j = 0; j < 8; j++) {
            float h1 = fmaxf(fmaf(bs.x, wa0[j], fmaf(bs.y, wa1[j], bs.z * wa2[j])), 0.f);
            acc[j].x = fmaf(h1, dt.x, acc[j].x);
            acc[j].y = fmaf(h1, dt.y, acc[j].y);
            acc[j].z = fmaf(h1, dt.z, acc[j].z);
            acc[j].w = fmaf(h1, dt.w, acc[j].w);
        }
    }
    uint32_t* t1 = &g_T1[(size_t)w * 512];
    uint32_t* t2 = &g_T2[(size_t)w * 512];
#pragma unroll
    for (int j = 0; j < 8; j++) {
        int idx = j * 32 + lane;
        float4 v = acc[j];
        float hx = bf_round(v.x), hy = bf_round(v.y);
        float hz = bf_round(v.z), hw = bf_round(v.w);
        uint2 w1 = make_uint2(pack_bf2(hx, hy), pack_bf2(hz, hw));
        uint2 w2 = make_uint2(pack_bf2(v.x - hx, v.y - hy),
                              pack_bf2(v.z - hz, v.w - hw));
        *(uint2*)&t1[idx * 2] = w1;
        *(uint2*)&t2[idx * 2] = w2;
    }
}

// ---------------------------------------------------------------------------
// K9: node GEMM h = T @ W^T * SCALE1 via 3xBF16 mma (M=64 tile, 128 thr)
// ---------------------------------------------------------------------------
#define ASTR 20

__global__ void __launch_bounds__(128) k_gemm_bf16(int M)
{
    __shared__ uint32_t A1s[64 * ASTR];
    __shared__ uint32_t A2s[64 * ASTR];
    __shared__ uint4    Bs[768];

    int tid = threadIdx.x, wid = tid >> 5, lane = tid & 31;
    int m0 = blockIdx.x * 64;

    float acc[12][4];
#pragma unroll
    for (int j = 0; j < 12; j++)
#pragma unroll
        for (int q = 0; q < 4; q++) acc[j][q] = 0.f;

    uint4 a1R[2], a2R[2], bR[6];
    const uint4 zero4 = make_uint4(0u, 0u, 0u, 0u);

#pragma unroll
    for (int it = 0; it < 2; it++) {
        int idx = tid + 128 * it;
        int r = idx >> 2, qc = idx & 3;
        int gm = m0 + r;
        if (gm < M) {
            a1R[it] = *(const uint4*)&g_T1[(size_t)gm * 512 + qc * 4];
            a2R[it] = *(const uint4*)&g_T2[(size_t)gm * 512 + qc * 4];
        } else { a1R[it] = zero4; a2R[it] = zero4; }
    }
#pragma unroll
    for (int it = 0; it < 6; it++)
        bR[it] = g_WB[tid + 128 * it];

    for (int kc = 0; kc < 32; kc++) {
        __syncthreads();
#pragma unroll
        for (int it = 0; it < 2; it++) {
            int idx = tid + 128 * it;
            int r = idx >> 2, qc = idx & 3;
            *(uint4*)&A1s[r * ASTR + qc * 4] = a1R[it];
            *(uint4*)&A2s[r * ASTR + qc * 4] = a2R[it];
        }
#pragma unroll
        for (int it = 0; it < 6; it++)
            Bs[tid + 128 * it] = bR[it];
        __syncthreads();

        if (kc < 31) {
            int kn = kc + 1;
#pragma unroll
            for (int it = 0; it < 2; it++) {
                int idx = tid + 128 * it;
                int r = idx >> 2, qc = idx & 3;
                int gm = m0 + r;
                if (gm < M) {
                    a1R[it] = *(const uint4*)&g_T1[(size_t)gm * 512 + kn * 16 + qc * 4];
                    a2R[it] = *(const uint4*)&g_T2[(size_t)gm * 512 + kn * 16 + qc * 4];
                } else { a1R[it] = zero4; a2R[it] = zero4; }
            }
#pragma unroll
            for (int it = 0; it < 6; it++)
                bR[it] = g_WB[kn * 768 + tid + 128 * it];
        }

#pragma unroll
        for (int ks = 0; ks < 2; ks++) {
            int ar = (wid * 16 + (lane >> 2)) * ASTR + ks * 8 + (lane & 3);
            uint32_t a10 = A1s[ar];
            uint32_t a11 = A1s[ar + 8 * ASTR];
            uint32_t a12 = A1s[ar + 4];
            uint32_t a13 = A1s[ar + 8 * ASTR + 4];
            uint32_t a20 = A2s[ar];
            uint32_t a21 = A2s[ar + 8 * ASTR];
            uint32_t a22 = A2s[ar + 4];
            uint32_t a23 = A2s[ar + 8 * ASTR + 4];
#pragma unroll
            for (int j = 0; j < 12; j++) {
                uint4 b = Bs[(ks * 12 + j) * 32 + lane];
                MMA_BF16(acc[j], a10, a11, a12, a13, b.x, b.y);
                MMA_BF16(acc[j], a10, a11, a12, a13, b.z, b.w);
                MMA_BF16(acc[j], a20, a21, a22, a23, b.x, b.y);
            }
        }
    }

    int r = lane >> 2, c2 = (lane & 3) * 2;
    int gm0 = m0 + wid * 16 + r;
#pragma unroll
    for (int j = 0; j < 12; j++) {
        int col = j * 8 + c2;
        if (gm0 < M)
            *(float2*)&g_h[(size_t)gm0 * 96 + col] =
                make_float2(acc[j][0] * SCALE1, acc[j][1] * SCALE1);
        if (gm0 + 8 < M)
            *(float2*)&g_h[(size_t)(gm0 + 8) * 96 + col] =
                make_float2(acc[j][2] * SCALE1, acc[j][3] * SCALE1);
    }
}

// ---------------------------------------------------------------------------
// K10: fused activation + z = y @ W2b^T via 3xBF16 mma (M=64 tile, 128 thr)
// ---------------------------------------------------------------------------
__global__ void __launch_bounds__(128) k_yzg(int N)
{
    __shared__ __nv_bfloat16 A1h[64 * 72];
    __shared__ __nv_bfloat16 A2h[64 * 72];

    int tid = threadIdx.x, wid = tid >> 5, lane = tid & 31;
    int n0 = blockIdx.x * 64;

    // produce y (activated) split into bf16 hi/lo
    for (int q = tid; q < 64 * 64; q += 128) {
        int row = q >> 6;
        int k = q & 63;
        int gn = n0 + row;
        float yv = 0.f;
        if (gn < N) {
            const float* hp = &g_h[(size_t)gn * 96];
            if (k < 32) {
                float s = hp[k];
                yv = (k < 16) ? fmaxf(s, 0.f) : fabsf(s);
            } else {
                int j = k - 32;
                float gv = hp[32 + j];
                float vv = hp[64 + j];
                float ga;
                if (j < 8)       ga = fmaxf(gv, 0.f);
                else if (j < 16) ga = tanhf(gv);
                else if (j < 24) ga = fmaxf(gv, 0.f);
                else             ga = tanhf(gv);
                yv = ga * vv;
            }
        }
        __nv_bfloat16 bh = __float2bfloat16_rn(yv);
        float hf = __bfloat162float(bh);
        A1h[row * 72 + k] = bh;
        A2h[row * 72 + k] = __float2bfloat16_rn(yv - hf);
    }
    __syncthreads();

    const uint32_t* A1w = (const uint32_t*)A1h;
    const uint32_t* A2w = (const uint32_t*)A2h;

#pragma unroll
    for (int nh = 0; nh < 2; nh++) {
        float acc[16][4];
#pragma unroll
        for (int j = 0; j < 16; j++)
#pragma unroll
            for (int q = 0; q < 4; q++) acc[j][q] = 0.f;

#pragma unroll
        for (int ks = 0; ks < 4; ks++) {
            int aw = (wid * 16 + (lane >> 2)) * 36 + ks * 8 + (lane & 3);
            uint32_t a10 = A1w[aw];
            uint32_t a11 = A1w[aw + 8 * 36];
            uint32_t a12 = A1w[aw + 4];
            uint32_t a13 = A1w[aw + 8 * 36 + 4];
            uint32_t a20 = A2w[aw];
            uint32_t a21 = A2w[aw + 8 * 36];
            uint32_t a22 = A2w[aw + 4];
            uint32_t a23 = A2w[aw + 8 * 36 + 4];
#pragma unroll
            for (int j = 0; j < 16; j++) {
                uint4 b = g_WB2[((nh * 16 + j) * 4 + ks) * 32 + lane];
                MMA_BF16(acc[j], a10, a11, a12, a13, b.x, b.y);
                MMA_BF16(acc[j], a10, a11, a12, a13, b.z, b.w);
                MMA_BF16(acc[j], a20, a21, a22, a23, b.x, b.y);
            }
        }
        int r = lane >> 2, c2 = (lane & 3) * 2;
        int gm0 = n0 + wid * 16 + r;
#pragma unroll
        for (int j = 0; j < 16; j++) {
            int col = nh * 128 + j * 8 + c2;
            if (gm0 < N)
                *(float2*)&g_z[(size_t)gm0 * 256 + col] =
                    make_float2(acc[j][0], acc[j][1]);
            if (gm0 + 8 < N)
                *(float2*)&g_z[(size_t)(gm0 + 8) * 256 + col] =
                    make_float2(acc[j][2], acc[j][3]);
        }
    }
}

// ---------------------------------------------------------------------------
// K11: final pass, warp per node over sorted edges
// ---------------------------------------------------------------------------
__global__ void __launch_bounds__(256) k_final(const float* __restrict__ W2a,
                                               float* __restrict__ out, int N)
{
    __shared__ float sW[768];
    for (int i = threadIdx.x; i < 768; i += 256) sW[i] = W2a[i];
    __syncthreads();

    int w = blockIdx.x * 8 + (threadIdx.x >> 5);
    int lane = threadIdx.x & 31;
    if (w >= N) return;
    int beg = g_off[w], end = g_off[w + 1];

    float w0[8], w1[8], w2[8];
#pragma unroll
    for (int j = 0; j < 8; j++) {
        int c = j * 32 + lane;
        w0[j] = sW[c]; w1[j] = sW[256 + c]; w2[j] = sW[512 + c];
    }

    float sum = 0.f;
    for (int i = beg; i < end; i++) {
        int src = g_srcS[i];
        float4 bs = *(const float4*)&g_basisS[(size_t)i * 4];
        const float* zp = &g_z[(size_t)src * 256];
#pragma unroll
        for (int j = 0; j < 8; j++) {
            int c = j * 32 + lane;
            float h2 = fmaxf(fmaf(bs.x, w0[j], fmaf(bs.y, w1[j], bs.z * w2[j])), 0.f);
            sum = fmaf(h2, zp[c], sum);
        }
    }
#pragma unroll
    for (int o = 16; o > 0; o >>= 1)
        sum += __shfl_down_sync(0xffffffffu, sum, o);
    if (lane == 0) out[w] = sum * SCALE2;
}

// ---------------------------------------------------------------------------
// Launch
// ---------------------------------------------------------------------------
extern "C" void kernel_launch(void* const* d_in, const int* in_sizes, int n_in,
                              void* d_out, int out_size)
{
    const float* edge_vec = (const float*)d_in[0];
    const float* edge_len = (const float*)d_in[1];
    const float* W1a      = (const float*)d_in[2];
    const float* W1b      = (const float*)d_in[3];
    const float* W2a      = (const float*)d_in[4];
    const float* W2b      = (const float*)d_in[5];
    const int*   esrc     = (const int*)d_in[6];
    const int*   edst     = (const int*)d_in[7];
    float* out = (float*)d_out;

    int E = in_sizes[1];
    int N = out_size;
    if (E > EMAX) E = EMAX;
    if (N > NMAX) N = NMAX;

    int nbA = (N + 1023) / 1024;
    int nbB = (N + 1 + 1023) / 1024;

    k_reord <<<(24576 + 255) / 256, 256>>>(W1b);
    k_reord2<<<(4096 + 255) / 256, 256>>>(W2b);
    k_zero  <<<(N + 255) / 256, 256>>>(N);
    k_hist  <<<(E + 255) / 256, 256>>>(edst, E);
    k_scanA <<<nbA, 1024>>>(N);
    k_scanB <<<nbB, 1024>>>(E, N);
    k_place <<<(E + 255) / 256, 256>>>(edst, esrc, edge_len, E);
    k_sh    <<<(E + 255) / 256, 256>>>(edge_vec, E);
    k_x     <<<(N + 15) / 16, 256>>>(N);
    k_dotsb <<<(E + 255) / 256, 256>>>(E);
    k_buildT<<<(N + 7) / 8, 256>>>(W1a, N);
    k_gemm_bf16<<<(N + 63) / 64, 128>>>(N);
    k_yzg   <<<(N + 63) / 64, 128>>>(N);
    k_final <<<(N + 7) / 8, 256>>>(W2a, out, N);
}

// round 7
// speedup vs baseline: 1.9812x; 1.0611x over previous
#include <cuda_runtime.h>
#include <cuda_bf16.h>
#include <math.h>
#include <stdint.h>

#define EMAX 250000
#define NMAX 25000

#define INV_NN   0.51298917604257706f   // 1/sqrt(3.8)
#define INV3     0.57735026918962576f
#define INV112   0.89285714285714285f   // 1/1.12
#define S3       1.7320508075688772f
#define S5       2.2360679774997896f
#define S7       2.6457513110645907f
#define S15      3.8729833462074170f
#define S105     10.246950765959598f
#define C358     2.0916500663351889f
#define C218     1.6201851746019651f
#define RS3      0.57735026918962576f
#define RS5      0.44721359549995794f
#define RS7      0.37796447300922720f
#define SCALE1   (INV3 * 0.5f / 16.0f * INV_NN)
#define SCALE2   (INV3 / 128.0f * INV_NN)

// ---------------------------------------------------------------------------
// Scratch
// ---------------------------------------------------------------------------
__device__ __align__(16) float g_shS    [EMAX * 16];  // dst-sorted sh
__device__ __align__(16) float g_x      [NMAX * 16];
__device__ __align__(16) float g_dotsS  [EMAX * 4];   // dst-sorted dots
__device__ __align__(16) float g_basisS [EMAX * 4];   // dst-sorted basis
__device__ __align__(16) float g_basis2S[EMAX * 4];   // src-sorted basis
__device__ int   g_hist [NMAX];
__device__ int   g_hist2[NMAX];
__device__ int   g_off  [NMAX + 1];
__device__ int   g_off2 [NMAX + 1];
__device__ int   g_cur  [NMAX];
__device__ int   g_cur2 [NMAX];
__device__ int   g_bsum [64];
__device__ int   g_srcS [EMAX];   // dst-sorted: src of edge
__device__ int   g_dst2S[EMAX];   // src-sorted: dst of edge
__device__ __align__(16) uint32_t g_T1 [(size_t)NMAX * 512];
__device__ __align__(16) uint32_t g_T2 [(size_t)NMAX * 512];
__device__ __align__(16) uint4 g_WB  [24576];  // W1b frag hi/lo
__device__ __align__(16) uint4 g_WB2 [4096];   // W2b frag hi/lo
__device__ __align__(16) float g_z   [(size_t)NMAX * 256];

// ---------------------------------------------------------------------------
// helpers
// ---------------------------------------------------------------------------
#define MMA_BF16(d, a0, a1, a2, a3, b0, b1)                                   \
    asm volatile("mma.sync.aligned.m16n8k16.row.col.f32.bf16.bf16.f32 "       \
        "{%0,%1,%2,%3},{%4,%5,%6,%7},{%8,%9},{%0,%1,%2,%3};"                  \
        : "+f"((d)[0]), "+f"((d)[1]), "+f"((d)[2]), "+f"((d)[3])              \
        : "r"(a0), "r"(a1), "r"(a2), "r"(a3), "r"(b0), "r"(b1))

__device__ __forceinline__ uint32_t pack_bf2(float a, float b) {
    __nv_bfloat162 t = __floats2bfloat162_rn(a, b);
    return *(uint32_t*)&t;
}
__device__ __forceinline__ float bf_round(float v) {
    __nv_bfloat16 t = __float2bfloat16_rn(v);
    return __bfloat162float(t);
}

// ---------------------------------------------------------------------------
// K0: zero both histograms + out
// ---------------------------------------------------------------------------
__global__ void k_zero(float* __restrict__ out, int N)
{
    int i = blockIdx.x * blockDim.x + threadIdx.x;
    if (i < N) { g_hist[i] = 0; g_hist2[i] = 0; out[i] = 0.f; }
}

// K1: both histograms
__global__ void k_hist(const int* __restrict__ edst,
                       const int* __restrict__ esrc, int E)
{
    int e = blockIdx.x * blockDim.x + threadIdx.x;
    if (e < E) {
        atomicAdd(&g_hist[edst[e]], 1);
        atomicAdd(&g_hist2[esrc[e]], 1);
    }
}

// ---------------------------------------------------------------------------
// K2a/K2b: two-phase scan, gridDim.y selects dst(0)/src(1) arrays
// ---------------------------------------------------------------------------
__global__ void __launch_bounds__(1024) k_scanA(int N)
{
    const int* hist = blockIdx.y ? g_hist2 : g_hist;
    int* off = blockIdx.y ? g_off2 : g_off;
    int b = blockIdx.x, t = threadIdx.x;
    int lane = t & 31, wid = t >> 5;
    int idx = b * 1024 + t;
    int v = (idx < N) ? hist[idx] : 0;
    int xv = v;
#pragma unroll
    for (int o = 1; o < 32; o <<= 1) {
        int tt = __shfl_up_sync(0xffffffffu, xv, o);
        if (lane >= o) xv += tt;
    }
    __shared__ int wsum[32];
    __shared__ int wpre[32];
    if (lane == 31) wsum[wid] = xv;
    __syncthreads();
    if (wid == 0) {
        int wv = wsum[lane];
        int xs = wv;
#pragma unroll
        for (int o = 1; o < 32; o <<= 1) {
            int tt = __shfl_up_sync(0xffffffffu, xs, o);
            if (lane >= o) xs += tt;
        }
        wpre[lane] = xs - wv;
    }
    __syncthreads();
    int incl = xv + wpre[wid];
    if (idx < N) off[idx] = incl - v;
    if (t == 1023) g_bsum[blockIdx.y * 32 + b] = incl;
}

__global__ void __launch_bounds__(1024) k_scanB(int E, int N)
{
    int y = blockIdx.y;
    int* off = y ? g_off2 : g_off;
    int* cur = y ? g_cur2 : g_cur;
    int b = blockIdx.x, t = threadIdx.x;
    int idx = b * 1024 + t;
    __shared__ int spre;
    if (t < 32) {
        int v = (t < b) ? g_bsum[y * 32 + t] : 0;
#pragma unroll
        for (int o = 16; o > 0; o >>= 1)
            v += __shfl_down_sync(0xffffffffu, v, o);
        if (t == 0) spre = v;
    }
    __syncthreads();
    if (idx < N) {
        int val = off[idx] + spre;
        off[idx] = val;
        cur[idx] = val;
    }
    if (idx == N) off[N] = E;
}

// ---------------------------------------------------------------------------
// K3: fused sort: sh + basis computed once, scattered to both orders
// ---------------------------------------------------------------------------
__global__ void k_sort(const int*   __restrict__ edst,
                       const int*   __restrict__ esrc,
                       const float* __restrict__ edge_len,
                       const float* __restrict__ edge_vec, int E)
{
    int e = blockIdx.x * blockDim.x + threadIdx.x;
    if (e >= E) return;
    int d = edst[e], s = esrc[e];
    int pos  = atomicAdd(&g_cur[d], 1);
    int pos2 = atomicAdd(&g_cur2[s], 1);

    float len = edge_len[e];
    float t0 = len * 0.5f;
    float t1 = (len - 2.0f) * 0.5f;
    float t2 = (len - 4.0f) * 0.5f;
    float4 bs = make_float4(expf(-t0 * t0) * INV112, expf(-t1 * t1) * INV112,
                            expf(-t2 * t2) * INV112, 0.f);
    *(float4*)&g_basisS [(size_t)pos  * 4] = bs;
    *(float4*)&g_basis2S[(size_t)pos2 * 4] = bs;
    g_srcS[pos]   = s;
    g_dst2S[pos2] = d;

    float x = edge_vec[e * 3 + 0];
    float y = edge_vec[e * 3 + 1];
    float z = edge_vec[e * 3 + 2];
    float inv = 1.0f / (sqrtf(x * x + y * y + z * z) + 1e-12f);
    x *= inv; y *= inv; z *= inv;
    float x2 = x * x, y2 = y * y, z2 = z * z;

    float4* shp = (float4*)&g_shS[(size_t)pos * 16];
    shp[0] = make_float4(1.0f, S3 * x, S3 * y, S3 * z);
    shp[1] = make_float4(S15 * x * z, S15 * x * y,
                         0.5f * S5 * (2.0f * y2 - x2 - z2), S15 * y * z);
    shp[2] = make_float4(0.5f * S15 * (z2 - x2),
                         C358 * x * (3.0f * z2 - x2),
                         S105 * x * y * z,
                         C218 * x * (4.0f * y2 - z2 - x2));
    shp[3] = make_float4(0.5f * S7 * y * (2.0f * y2 - 3.0f * z2 - 3.0f * x2),
                         C218 * z * (4.0f * y2 - z2 - x2),
                         0.5f * S105 * y * (z2 - x2),
                         C358 * z * (z2 - 3.0f * x2));
}

// ---------------------------------------------------------------------------
// K4: x[n,c] gather-sum over contiguous dst-sorted sh
// ---------------------------------------------------------------------------
__global__ void __launch_bounds__(256) k_x(int N)
{
    int n = blockIdx.x * 16 + (threadIdx.x >> 4);
    int c = threadIdx.x & 15;
    if (n >= N) return;
    int beg = g_off[n], end = g_off[n + 1];
    float acc = 0.f;
    for (int i = beg; i < end; i++)
        acc += g_shS[(size_t)i * 16 + c];
    g_x[n * 16 + c] = acc;
}

// ---------------------------------------------------------------------------
// K5: W1b -> bf16 hi/lo frag order
// ---------------------------------------------------------------------------
__global__ void k_reord(const float* __restrict__ W1b)
{
    int idx = blockIdx.x * blockDim.x + threadIdx.x;
    if (idx >= 24576) return;
    int lane = idx & 31;
    int t = idx >> 5;
    int j = t % 12;
    int t2 = t / 12;
    int n = j * 8 + (lane >> 2);
    int kbase = t2 * 16 + (lane & 3) * 2;

    float v[4], h[4];
    int kks[4] = {kbase, kbase + 1, kbase + 8, kbase + 9};
#pragma unroll
    for (int q = 0; q < 4; q++) {
        int kk = kks[q];
        int c = kk >> 2, p = kk & 3;
        v[q] = W1b[c * 384 + p * 96 + n];
        h[q] = bf_round(v[q]);
    }
    uint4 o;
    o.x = pack_bf2(h[0], h[1]);
    o.y = pack_bf2(h[2], h[3]);
    o.z = pack_bf2(v[0] - h[0], v[1] - h[1]);
    o.w = pack_bf2(v[2] - h[2], v[3] - h[3]);
    g_WB[idx] = o;
}

// K5b: W2b -> bf16 hi/lo frag order
__global__ void k_reord2(const float* __restrict__ W2b)
{
    int idx = blockIdx.x * blockDim.x + threadIdx.x;
    if (idx >= 4096) return;
    int lane = idx & 31;
    int t = idx >> 5;
    int ks = t & 3;
    int j  = t >> 2;
    int n = j * 8 + (lane >> 2);
    int k0 = ks * 16 + (lane & 3) * 2;
    float v00 = W2b[n * 64 + k0],     v01 = W2b[n * 64 + k0 + 1];
    float v10 = W2b[n * 64 + k0 + 8], v11 = W2b[n * 64 + k0 + 9];
    float h00 = bf_round(v00), h01 = bf_round(v01);
    float h10 = bf_round(v10), h11 = bf_round(v11);
    uint4 o;
    o.x = pack_bf2(h00, h01);
    o.y = pack_bf2(h10, h11);
    o.z = pack_bf2(v00 - h00, v01 - h01);
    o.w = pack_bf2(v10 - h10, v11 - h11);
    g_WB2[idx] = o;
}

// ---------------------------------------------------------------------------
// K6: per-edge dots (dst-sorted streams)
// ---------------------------------------------------------------------------
__global__ void k_dotsb(int E)
{
    int i = blockIdx.x * blockDim.x + threadIdx.x;
    if (i >= E) return;
    int src = g_srcS[i];
    const float4* shp = (const float4*)&g_shS[(size_t)i * 16];
    const float4* xp  = (const float4*)&g_x[(size_t)src * 16];
    float4 s0 = shp[0], s1 = shp[1], s2 = shp[2], s3 = shp[3];
    float4 x0 = xp[0],  x1 = xp[1],  x2 = xp[2],  x3 = xp[3];

    float d0 = x0.x * s0.x;
    float d1 = (x0.y * s0.y + x0.z * s0.z + x0.w * s0.w) * RS3;
    float d2 = (x1.x * s1.x + x1.y * s1.y + x1.z * s1.z + x1.w * s1.w + x2.x * s2.x) * RS5;
    float d3 = (x2.y * s2.y + x2.z * s2.z + x2.w * s2.w +
                x3.x * s3.x + x3.y * s3.y + x3.z * s3.z + x3.w * s3.w) * RS7;
    *(float4*)&g_dotsS[(size_t)i * 4] =
        make_float4(d0 * INV_NN, d1 * INV_NN, d2 * INV_NN, d3 * INV_NN);
}

// ---------------------------------------------------------------------------
// K7: build T (streaming); store bf16 hi/lo planes
// ---------------------------------------------------------------------------
__global__ void __launch_bounds__(256) k_buildT(const float* __restrict__ W1a, int N)
{
    __shared__ float sW[768];
    for (int i = threadIdx.x; i < 768; i += 256) sW[i] = W1a[i];
    __syncthreads();

    int w = blockIdx.x * 8 + (threadIdx.x >> 5);
    int lane = threadIdx.x & 31;
    if (w >= N) return;
    int beg = g_off[w], end = g_off[w + 1];

    float wa0[8], wa1[8], wa2[8];
#pragma unroll
    for (int j = 0; j < 8; j++) {
        int c = j * 32 + lane;
        wa0[j] = sW[c]; wa1[j] = sW[256 + c]; wa2[j] = sW[512 + c];
    }
    float4 acc[8];
#pragma unroll
    for (int j = 0; j < 8; j++) acc[j] = make_float4(0.f, 0.f, 0.f, 0.f);

    for (int i = beg; i < end; i++) {
        float4 bs = *(const float4*)&g_basisS[(size_t)i * 4];
        float4 dt = *(const float4*)&g_dotsS[(size_t)i * 4];
#pragma unroll
        for (int j = 0; j < 8; j++) {
            float h1 = fmaxf(fmaf(bs.x, wa0[j], fmaf(bs.y, wa1[j], bs.z * wa2[j])), 0.f);
            acc[j].x = fmaf(h1, dt.x, acc[j].x);
            acc[j].y = fmaf(h1, dt.y, acc[j].y);
            acc[j].z = fmaf(h1, dt.z, acc[j].z);
            acc[j].w = fmaf(h1, dt.w, acc[j].w);
        }
    }
    uint32_t* t1 = &g_T1[(size_t)w * 512];
    uint32_t* t2 = &g_T2[(size_t)w * 512];
#pragma unroll
    for (int j = 0; j < 8; j++) {
        int idx = j * 32 + lane;
        float4 v = acc[j];
        float hx = bf_round(v.x), hy = bf_round(v.y);
        float hz = bf_round(v.z), hw = bf_round(v.w);
        uint2 w1 = make_uint2(pack_bf2(hx, hy), pack_bf2(hz, hw));
        uint2 w2 = make_uint2(pack_bf2(v.x - hx, v.y - hy),
                              pack_bf2(v.z - hz, v.w - hw));
        *(uint2*)&t1[idx * 2] = w1;
        *(uint2*)&t2[idx * 2] = w2;
    }
}

// ---------------------------------------------------------------------------
// K8: fused GEMM1 (h) -> activation (y) -> GEMM2 (z), M=64 tile, 128 thr
// ---------------------------------------------------------------------------
#define ASTR 20

__global__ void __launch_bounds__(128) k_gemm_fused(int M)
{
    __shared__ uint32_t A1s[64 * ASTR];
    __shared__ uint32_t A2s[64 * ASTR];
    __shared__ uint4    Bs[768];
    __shared__ uint32_t Y1[64 * 36];
    __shared__ uint32_t Y2[64 * 36];

    int tid = threadIdx.x, wid = tid >> 5, lane = tid & 31;
    int m0 = blockIdx.x * 64;

    float acc[12][4];
#pragma unroll
    for (int j = 0; j < 12; j++)
#pragma unroll
        for (int q = 0; q < 4; q++) acc[j][q] = 0.f;

    uint4 a1R[2], a2R[2], bR[6];
    const uint4 zero4 = make_uint4(0u, 0u, 0u, 0u);

#pragma unroll
    for (int it = 0; it < 2; it++) {
        int idx = tid + 128 * it;
        int r = idx >> 2, qc = idx & 3;
        int gm = m0 + r;
        if (gm < M) {
            a1R[it] = *(const uint4*)&g_T1[(size_t)gm * 512 + qc * 4];
            a2R[it] = *(const uint4*)&g_T2[(size_t)gm * 512 + qc * 4];
        } else { a1R[it] = zero4; a2R[it] = zero4; }
    }
#pragma unroll
    for (int it = 0; it < 6; it++)
        bR[it] = g_WB[tid + 128 * it];

    for (int kc = 0; kc < 32; kc++) {
        __syncthreads();
#pragma unroll
        for (int it = 0; it < 2; it++) {
            int idx = tid + 128 * it;
            int r = idx >> 2, qc = idx & 3;
            *(uint4*)&A1s[r * ASTR + qc * 4] = a1R[it];
            *(uint4*)&A2s[r * ASTR + qc * 4] = a2R[it];
        }
#pragma unroll
        for (int it = 0; it < 6; it++)
            Bs[tid + 128 * it] = bR[it];
        __syncthreads();

        if (kc < 31) {
            int kn = kc + 1;
#pragma unroll
            for (int it = 0; it < 2; it++) {
                int idx = tid + 128 * it;
                int r = idx >> 2, qc = idx & 3;
                int gm = m0 + r;
                if (gm < M) {
                    a1R[it] = *(const uint4*)&g_T1[(size_t)gm * 512 + kn * 16 + qc * 4];
                    a2R[it] = *(const uint4*)&g_T2[(size_t)gm * 512 + kn * 16 + qc * 4];
                } else { a1R[it] = zero4; a2R[it] = zero4; }
            }
#pragma unroll
            for (int it = 0; it < 6; it++)
                bR[it] = g_WB[kn * 768 + tid + 128 * it];
        }

#pragma unroll
        for (int ks = 0; ks < 2; ks++) {
            int ar = (wid * 16 + (lane >> 2)) * ASTR + ks * 8 + (lane & 3);
            uint32_t a10 = A1s[ar];
            uint32_t a11 = A1s[ar + 8 * ASTR];
            uint32_t a12 = A1s[ar + 4];
            uint32_t a13 = A1s[ar + 8 * ASTR + 4];
            uint32_t a20 = A2s[ar];
            uint32_t a21 = A2s[ar + 8 * ASTR];
            uint32_t a22 = A2s[ar + 4];
            uint32_t a23 = A2s[ar + 8 * ASTR + 4];
#pragma unroll
            for (int j = 0; j < 12; j++) {
                uint4 b = Bs[(ks * 12 + j) * 32 + lane];
                MMA_BF16(acc[j], a10, a11, a12, a13, b.x, b.y);
                MMA_BF16(acc[j], a10, a11, a12, a13, b.z, b.w);
                MMA_BF16(acc[j], a20, a21, a22, a23, b.x, b.y);
            }
        }
    }

    // ---- activation: h fragments -> y, bf16-split into Y1/Y2 smem
    int r0 = wid * 16 + (lane >> 2);
#pragma unroll
    for (int half = 0; half < 2; half++) {
        int row = r0 + half * 8;
#pragma unroll
        for (int j = 0; j < 8; j++) {
            float v0, v1;
            if (j < 4) {
                float s0 = acc[j][half * 2] * SCALE1;
                float s1 = acc[j][half * 2 + 1] * SCALE1;
                if (j < 2) { v0 = fmaxf(s0, 0.f); v1 = fmaxf(s1, 0.f); }
                else       { v0 = fabsf(s0);      v1 = fabsf(s1); }
            } else {
                float g0 = acc[j][half * 2] * SCALE1;
                float g1 = acc[j][half * 2 + 1] * SCALE1;
                float q0 = acc[j + 4][half * 2] * SCALE1;
                float q1 = acc[j + 4][half * 2 + 1] * SCALE1;
                float a0, a1;
                if ((j & 1) == 0) { a0 = fmaxf(g0, 0.f); a1 = fmaxf(g1, 0.f); }
                else              { a0 = tanhf(g0);      a1 = tanhf(g1); }
                v0 = a0 * q0; v1 = a1 * q1;
            }
            float h0 = bf_round(v0), h1 = bf_round(v1);
            int widx = row * 36 + j * 4 + (lane & 3);
            Y1[widx] = pack_bf2(h0, h1);
            Y2[widx] = pack_bf2(v0 - h0, v1 - h1);
        }
    }
    __syncthreads();

    // ---- GEMM2: z = y @ W2b^T (K=64, N=256)
#pragma unroll
    for (int nh = 0; nh < 2; nh++) {
        float zac[16][4];
#pragma unroll
        for (int j = 0; j < 16; j++)
#pragma unroll
            for (int q = 0; q < 4; q++) zac[j][q] = 0.f;

#pragma unroll
        for (int ks = 0; ks < 4; ks++) {
            int aw = (wid * 16 + (lane >> 2)) * 36 + ks * 8 + (lane & 3);
            uint32_t a10 = Y1[aw];
            uint32_t a11 = Y1[aw + 8 * 36];
            uint32_t a12 = Y1[aw + 4];
            uint32_t a13 = Y1[aw + 8 * 36 + 4];
            uint32_t a20 = Y2[aw];
            uint32_t a21 = Y2[aw + 8 * 36];
            uint32_t a22 = Y2[aw + 4];
            uint32_t a23 = Y2[aw + 8 * 36 + 4];
#pragma unroll
            for (int j = 0; j < 16; j++) {
                uint4 b = g_WB2[((nh * 16 + j) * 4 + ks) * 32 + lane];
                MMA_BF16(zac[j], a10, a11, a12, a13, b.x, b.y);
                MMA_BF16(zac[j], a10, a11, a12, a13, b.z, b.w);
                MMA_BF16(zac[j], a20, a21, a22, a23, b.x, b.y);
            }
        }
        int rr = lane >> 2, c2 = (lane & 3) * 2;
        int gm0 = m0 + wid * 16 + rr;
#pragma unroll
        for (int j = 0; j < 16; j++) {
            int col = nh * 128 + j * 8 + c2;
            if (gm0 < M)
                *(float2*)&g_z[(size_t)gm0 * 256 + col] =
                    make_float2(zac[j][0], zac[j][1]);
            if (gm0 + 8 < M)
                *(float2*)&g_z[(size_t)(gm0 + 8) * 256 + col] =
                    make_float2(zac[j][2], zac[j][3]);
        }
    }
}

// ---------------------------------------------------------------------------
// K9: final pass, warp per SRC node; z in registers; atomicAdd to out[dst]
// ---------------------------------------------------------------------------
__global__ void __launch_bounds__(256) k_final(const float* __restrict__ W2a,
                                               float* __restrict__ out, int N)
{
    __shared__ float sW[768];
    for (int i = threadIdx.x; i < 768; i += 256) sW[i] = W2a[i];
    __syncthreads();

    int w = blockIdx.x * 8 + (threadIdx.x >> 5);
    int lane = threadIdx.x & 31;
    if (w >= N) return;
    int beg = g_off2[w], end = g_off2[w + 1];
    if (beg == end) return;

    float w0[8], w1[8], w2[8], zr[8];
    const float* zp = &g_z[(size_t)w * 256];
#pragma unroll
    for (int j = 0; j < 8; j++) {
        int c = j * 32 + lane;
        w0[j] = sW[c]; w1[j] = sW[256 + c]; w2[j] = sW[512 + c];
        zr[j] = zp[c];
    }

    for (int i = beg; i < end; i++) {
        float4 bs = *(const float4*)&g_basis2S[(size_t)i * 4];
        int dst = g_dst2S[i];
        float sum = 0.f;
#pragma unroll
        for (int j = 0; j < 8; j++) {
            float h2 = fmaxf(fmaf(bs.x, w0[j], fmaf(bs.y, w1[j], bs.z * w2[j])), 0.f);
            sum = fmaf(h2, zr[j], sum);
        }
#pragma unroll
        for (int o = 16; o > 0; o >>= 1)
            sum += __shfl_down_sync(0xffffffffu, sum, o);
        if (lane == 0) atomicAdd(&out[dst], sum * SCALE2);
    }
}

// ---------------------------------------------------------------------------
// Launch
// ---------------------------------------------------------------------------
extern "C" void kernel_launch(void* const* d_in, const int* in_sizes, int n_in,
                              void* d_out, int out_size)
{
    const float* edge_vec = (const float*)d_in[0];
    const float* edge_len = (const float*)d_in[1];
    const float* W1a      = (const float*)d_in[2];
    const float* W1b      = (const float*)d_in[3];
    const float* W2a      = (const float*)d_in[4];
    const float* W2b      = (const float*)d_in[5];
    const int*   esrc     = (const int*)d_in[6];
    const int*   edst     = (const int*)d_in[7];
    float* out = (float*)d_out;

    int E = in_sizes[1];
    int N = out_size;
    if (E > EMAX) E = EMAX;
    if (N > NMAX) N = NMAX;

    int nbA = (N + 1023) / 1024;
    int nbB = (N + 1 + 1023) / 1024;

    k_reord <<<(24576 + 255) / 256, 256>>>(W1b);
    k_reord2<<<(4096 + 255) / 256, 256>>>(W2b);
    k_zero  <<<(N + 255) / 256, 256>>>(out, N);
    k_hist  <<<(E + 255) / 256, 256>>>(edst, esrc, E);
    k_scanA <<<dim3(nbA, 2), 1024>>>(N);
    k_scanB <<<dim3(nbB, 2), 1024>>>(E, N);
    k_sort  <<<(E + 255) / 256, 256>>>(edst, esrc, edge_len, edge_vec, E);
    k_x     <<<(N + 15) / 16, 256>>>(N);
    k_dotsb <<<(E + 255) / 256, 256>>>(E);
    k_buildT<<<(N + 7) / 8, 256>>>(W1a, N);
    k_gemm_fused<<<(N + 63) / 64, 128>>>(N);
    k_final <<<(N + 7) / 8, 256>>>(W2a, out, N);
}

// round 8
// speedup vs baseline: 2.0221x; 1.0206x over previous
#include <cuda_runtime.h>
#include <cuda_bf16.h>
#include <math.h>
#include <stdint.h>

#define EMAX 250000
#define NMAX 25000

#define INV_NN   0.51298917604257706f   // 1/sqrt(3.8)
#define INV3     0.57735026918962576f
#define INV112   0.89285714285714285f   // 1/1.12
#define S3       1.7320508075688772f
#define S5       2.2360679774997896f
#define S7       2.6457513110645907f
#define S15      3.8729833462074170f
#define S105     10.246950765959598f
#define C358     2.0916500663351889f
#define C218     1.6201851746019651f
#define RS3      0.57735026918962576f
#define RS5      0.44721359549995794f
#define RS7      0.37796447300922720f
#define SCALE1   (INV3 * 0.5f / 16.0f * INV_NN)
#define SCALE2   (INV3 / 128.0f * INV_NN)

// ---------------------------------------------------------------------------
// Scratch
// ---------------------------------------------------------------------------
__device__ __align__(16) float g_shS    [EMAX * 16];  // dst-sorted sh
__device__ __align__(16) float g_x      [NMAX * 16];
__device__ __align__(16) float g_dotsS  [EMAX * 4];   // dst-sorted dots
__device__ __align__(16) float g_basisS [EMAX * 4];   // dst-sorted basis
__device__ __align__(16) float g_basis2S[EMAX * 4];   // src-sorted basis
__device__ int   g_hist [NMAX];
__device__ int   g_hist2[NMAX];
__device__ int   g_off  [NMAX + 1];
__device__ int   g_off2 [NMAX + 1];
__device__ int   g_cur  [NMAX];
__device__ int   g_cur2 [NMAX];
__device__ volatile int g_part[64];
__device__ volatile int g_flag[64];
__device__ int   g_srcS [EMAX];   // dst-sorted: src of edge
__device__ int   g_dst2S[EMAX];   // src-sorted: dst of edge
__device__ __align__(16) uint32_t g_T1 [(size_t)NMAX * 512];
__device__ __align__(16) uint32_t g_T2 [(size_t)NMAX * 512];
__device__ __align__(16) uint4 g_WB  [24576];  // W1b frag hi/lo
__device__ __align__(16) uint4 g_WB2 [4096];   // W2b frag hi/lo
__device__ __align__(16) __nv_bfloat16 g_zb [(size_t)NMAX * 256];

// ---------------------------------------------------------------------------
// helpers
// ---------------------------------------------------------------------------
#define MMA_BF16(d, a0, a1, a2, a3, b0, b1)                                   \
    asm volatile("mma.sync.aligned.m16n8k16.row.col.f32.bf16.bf16.f32 "       \
        "{%0,%1,%2,%3},{%4,%5,%6,%7},{%8,%9},{%0,%1,%2,%3};"                  \
        : "+f"((d)[0]), "+f"((d)[1]), "+f"((d)[2]), "+f"((d)[3])              \
        : "r"(a0), "r"(a1), "r"(a2), "r"(a3), "r"(b0), "r"(b1))

__device__ __forceinline__ uint32_t pack_bf2(float a, float b) {
    __nv_bfloat162 t = __floats2bfloat162_rn(a, b);
    return *(uint32_t*)&t;
}
__device__ __forceinline__ float bf_round(float v) {
    __nv_bfloat16 t = __float2bfloat16_rn(v);
    return __bfloat162float(t);
}

// ---------------------------------------------------------------------------
// K0: zero histograms + out + scan flags
// ---------------------------------------------------------------------------
__global__ void k_zero(float* __restrict__ out, int N)
{
    int i = blockIdx.x * blockDim.x + threadIdx.x;
    if (i < N) { g_hist[i] = 0; g_hist2[i] = 0; out[i] = 0.f; }
    if (i < 64) { g_flag[i] = 0; g_part[i] = 0; }
}

// ---------------------------------------------------------------------------
// K1: histograms + weight reorders (independent blocks share the launch)
// ---------------------------------------------------------------------------
__global__ void k_histR(const int* __restrict__ edst,
                        const int* __restrict__ esrc, int E, int nbE,
                        const float* __restrict__ W1b,
                        const float* __restrict__ W2b)
{
    int b = blockIdx.x;
    int tid = threadIdx.x;
    if (b < nbE) {
        int e = b * 256 + tid;
        if (e < E) {
            atomicAdd(&g_hist[edst[e]], 1);
            atomicAdd(&g_hist2[esrc[e]], 1);
        }
        return;
    }
    if (b < nbE + 96) {
        // W1b -> bf16 hi/lo frag order (m16n8k16 B operand)
        int idx = (b - nbE) * 256 + tid;
        int lane = idx & 31;
        int t = idx >> 5;
        int j = t % 12;
        int t2 = t / 12;
        int n = j * 8 + (lane >> 2);
        int kbase = t2 * 16 + (lane & 3) * 2;
        float v[4], h[4];
        int kks[4] = {kbase, kbase + 1, kbase + 8, kbase + 9};
#pragma unroll
        for (int q = 0; q < 4; q++) {
            int kk = kks[q];
            int c = kk >> 2, p = kk & 3;
            v[q] = W1b[c * 384 + p * 96 + n];
            h[q] = bf_round(v[q]);
        }
        uint4 o;
        o.x = pack_bf2(h[0], h[1]);
        o.y = pack_bf2(h[2], h[3]);
        o.z = pack_bf2(v[0] - h[0], v[1] - h[1]);
        o.w = pack_bf2(v[2] - h[2], v[3] - h[3]);
        g_WB[idx] = o;
        return;
    }
    {
        // W2b -> bf16 hi/lo frag order
        int idx = (b - nbE - 96) * 256 + tid;
        int lane = idx & 31;
        int t = idx >> 5;
        int ks = t & 3;
        int j  = t >> 2;
        int n = j * 8 + (lane >> 2);
        int k0 = ks * 16 + (lane & 3) * 2;
        float v00 = W2b[n * 64 + k0],     v01 = W2b[n * 64 + k0 + 1];
        float v10 = W2b[n * 64 + k0 + 8], v11 = W2b[n * 64 + k0 + 9];
        float h00 = bf_round(v00), h01 = bf_round(v01);
        float h10 = bf_round(v10), h11 = bf_round(v11);
        uint4 o;
        o.x = pack_bf2(h00, h01);
        o.y = pack_bf2(h10, h11);
        o.z = pack_bf2(v00 - h00, v01 - h01);
        o.w = pack_bf2(v10 - h10, v11 - h11);
        g_WB2[idx] = o;
    }
}

// ---------------------------------------------------------------------------
// K2: single-kernel exclusive scan with decoupled block prefix
//     grid (25, 2): y=0 dst arrays, y=1 src arrays; 50 blocks co-resident
// ---------------------------------------------------------------------------
__global__ void __launch_bounds__(1024) k_scan(int E, int N)
{
    int y = blockIdx.y;
    const int* hist = y ? g_hist2 : g_hist;
    int* off = y ? g_off2 : g_off;
    int* cur = y ? g_cur2 : g_cur;
    int b = blockIdx.x, t = threadIdx.x;
    int lane = t & 31, wid = t >> 5;
    int idx = b * 1024 + t;
    int v = (idx < N) ? hist[idx] : 0;
    int xv = v;
#pragma unroll
    for (int o = 1; o < 32; o <<= 1) {
        int tt = __shfl_up_sync(0xffffffffu, xv, o);
        if (lane >= o) xv += tt;
    }
    __shared__ int wsum[32];
    __shared__ int wpre[32];
    __shared__ int spre;
    if (lane == 31) wsum[wid] = xv;
    __syncthreads();
    if (wid == 0) {
        int wv = wsum[lane];
        int xs = wv;
#pragma unroll
        for (int o = 1; o < 32; o <<= 1) {
            int tt = __shfl_up_sync(0xffffffffu, xs, o);
            if (lane >= o) xs += tt;
        }
        wpre[lane] = xs - wv;
    }
    __syncthreads();
    int incl = xv + wpre[wid];
    // publish block total (thread 1023 holds it)
    if (t == 1023) {
        g_part[y * 32 + b] = incl;
        __threadfence();
        g_flag[y * 32 + b] = 1;
    }
    // one warp collects predecessor partials
    if (wid == 1) {
        int pv = 0;
        if (lane < b) {
            while (g_flag[y * 32 + lane] == 0) { }
            pv = g_part[y * 32 + lane];
        }
#pragma unroll
        for (int o = 16; o > 0; o >>= 1)
            pv += __shfl_down_sync(0xffffffffu, pv, o);
        if (lane == 0) spre = pv;
    }
    __syncthreads();
    int val = incl - v + spre;
    if (idx < N) { off[idx] = val; cur[idx] = val; }
    if (idx == N) off[N] = E;
}

// ---------------------------------------------------------------------------
// K3: fused sort: sh + basis computed once, scattered to both orders
// ---------------------------------------------------------------------------
__global__ void k_sort(const int*   __restrict__ edst,
                       const int*   __restrict__ esrc,
                       const float* __restrict__ edge_len,
                       const float* __restrict__ edge_vec, int E)
{
    int e = blockIdx.x * blockDim.x + threadIdx.x;
    if (e >= E) return;
    int d = edst[e], s = esrc[e];
    int pos  = atomicAdd(&g_cur[d], 1);
    int pos2 = atomicAdd(&g_cur2[s], 1);

    float len = edge_len[e];
    float t0 = len * 0.5f;
    float t1 = (len - 2.0f) * 0.5f;
    float t2 = (len - 4.0f) * 0.5f;
    float4 bs = make_float4(expf(-t0 * t0) * INV112, expf(-t1 * t1) * INV112,
                            expf(-t2 * t2) * INV112, 0.f);
    *(float4*)&g_basisS [(size_t)pos  * 4] = bs;
    *(float4*)&g_basis2S[(size_t)pos2 * 4] = bs;
    g_srcS[pos]   = s;
    g_dst2S[pos2] = d;

    float x = edge_vec[e * 3 + 0];
    float y = edge_vec[e * 3 + 1];
    float z = edge_vec[e * 3 + 2];
    float inv = 1.0f / (sqrtf(x * x + y * y + z * z) + 1e-12f);
    x *= inv; y *= inv; z *= inv;
    float x2 = x * x, y2 = y * y, z2 = z * z;

    float4* shp = (float4*)&g_shS[(size_t)pos * 16];
    shp[0] = make_float4(1.0f, S3 * x, S3 * y, S3 * z);
    shp[1] = make_float4(S15 * x * z, S15 * x * y,
                         0.5f * S5 * (2.0f * y2 - x2 - z2), S15 * y * z);
    shp[2] = make_float4(0.5f * S15 * (z2 - x2),
                         C358 * x * (3.0f * z2 - x2),
                         S105 * x * y * z,
                         C218 * x * (4.0f * y2 - z2 - x2));
    shp[3] = make_float4(0.5f * S7 * y * (2.0f * y2 - 3.0f * z2 - 3.0f * x2),
                         C218 * z * (4.0f * y2 - z2 - x2),
                         0.5f * S105 * y * (z2 - x2),
                         C358 * z * (z2 - 3.0f * x2));
}

// ---------------------------------------------------------------------------
// K4: x[n,c] gather-sum over contiguous dst-sorted sh
// ---------------------------------------------------------------------------
__global__ void __launch_bounds__(256) k_x(int N)
{
    int n = blockIdx.x * 16 + (threadIdx.x >> 4);
    int c = threadIdx.x & 15;
    if (n >= N) return;
    int beg = g_off[n], end = g_off[n + 1];
    float acc = 0.f;
    for (int i = beg; i < end; i++)
        acc += g_shS[(size_t)i * 16 + c];
    g_x[n * 16 + c] = acc;
}

// ---------------------------------------------------------------------------
// K5: per-edge dots (dst-sorted streams)
// ---------------------------------------------------------------------------
__global__ void k_dotsb(int E)
{
    int i = blockIdx.x * blockDim.x + threadIdx.x;
    if (i >= E) return;
    int src = g_srcS[i];
    const float4* shp = (const float4*)&g_shS[(size_t)i * 16];
    const float4* xp  = (const float4*)&g_x[(size_t)src * 16];
    float4 s0 = shp[0], s1 = shp[1], s2 = shp[2], s3 = shp[3];
    float4 x0 = xp[0],  x1 = xp[1],  x2 = xp[2],  x3 = xp[3];

    float d0 = x0.x * s0.x;
    float d1 = (x0.y * s0.y + x0.z * s0.z + x0.w * s0.w) * RS3;
    float d2 = (x1.x * s1.x + x1.y * s1.y + x1.z * s1.z + x1.w * s1.w + x2.x * s2.x) * RS5;
    float d3 = (x2.y * s2.y + x2.z * s2.z + x2.w * s2.w +
                x3.x * s3.x + x3.y * s3.y + x3.z * s3.z + x3.w * s3.w) * RS7;
    *(float4*)&g_dotsS[(size_t)i * 4] =
        make_float4(d0 * INV_NN, d1 * INV_NN, d2 * INV_NN, d3 * INV_NN);
}

// ---------------------------------------------------------------------------
// K6: build T (streaming); store bf16 hi/lo planes
// ---------------------------------------------------------------------------
__global__ void __launch_bounds__(256) k_buildT(const float* __restrict__ W1a, int N)
{
    __shared__ float sW[768];
    for (int i = threadIdx.x; i < 768; i += 256) sW[i] = W1a[i];
    __syncthreads();

    int w = blockIdx.x * 8 + (threadIdx.x >> 5);
    int lane = threadIdx.x & 31;
    if (w >= N) return;
    int beg = g_off[w], end = g_off[w + 1];

    float wa0[8], wa1[8], wa2[8];
#pragma unroll
    for (int j = 0; j < 8; j++) {
        int c = j * 32 + lane;
        wa0[j] = sW[c]; wa1[j] = sW[256 + c]; wa2[j] = sW[512 + c];
    }
    float4 acc[8];
#pragma unroll
    for (int j = 0; j < 8; j++) acc[j] = make_float4(0.f, 0.f, 0.f, 0.f);

    for (int i = beg; i < end; i++) {
        float4 bs = *(const float4*)&g_basisS[(size_t)i * 4];
        float4 dt = *(const float4*)&g_dotsS[(size_t)i * 4];
#pragma unroll
        for (int j = 0; j < 8; j++) {
            float h1 = fmaxf(fmaf(bs.x, wa0[j], fmaf(bs.y, wa1[j], bs.z * wa2[j])), 0.f);
            acc[j].x = fmaf(h1, dt.x, acc[j].x);
            acc[j].y = fmaf(h1, dt.y, acc[j].y);
            acc[j].z = fmaf(h1, dt.z, acc[j].z);
            acc[j].w = fmaf(h1, dt.w, acc[j].w);
        }
    }
    uint32_t* t1 = &g_T1[(size_t)w * 512];
    uint32_t* t2 = &g_T2[(size_t)w * 512];
#pragma unroll
    for (int j = 0; j < 8; j++) {
        int idx = j * 32 + lane;
        float4 v = acc[j];
        float hx = bf_round(v.x), hy = bf_round(v.y);
        float hz = bf_round(v.z), hw = bf_round(v.w);
        uint2 w1 = make_uint2(pack_bf2(hx, hy), pack_bf2(hz, hw));
        uint2 w2 = make_uint2(pack_bf2(v.x - hx, v.y - hy),
                              pack_bf2(v.z - hz, v.w - hw));
        *(uint2*)&t1[idx * 2] = w1;
        *(uint2*)&t2[idx * 2] = w2;
    }
}

// ---------------------------------------------------------------------------
// K7: fused GEMM1 (h) -> activation (y) -> GEMM2 (z, bf16 out)
// ---------------------------------------------------------------------------
#define ASTR 20

__global__ void __launch_bounds__(128) k_gemm_fused(int M)
{
    __shared__ uint32_t A1s[64 * ASTR];
    __shared__ uint32_t A2s[64 * ASTR];
    __shared__ uint4    Bs[768];
    __shared__ uint32_t Y1[64 * 36];
    __shared__ uint32_t Y2[64 * 36];

    int tid = threadIdx.x, wid = tid >> 5, lane = tid & 31;
    int m0 = blockIdx.x * 64;

    float acc[12][4];
#pragma unroll
    for (int j = 0; j < 12; j++)
#pragma unroll
        for (int q = 0; q < 4; q++) acc[j][q] = 0.f;

    uint4 a1R[2], a2R[2], bR[6];
    const uint4 zero4 = make_uint4(0u, 0u, 0u, 0u);

#pragma unroll
    for (int it = 0; it < 2; it++) {
        int idx = tid + 128 * it;
        int r = idx >> 2, qc = idx & 3;
        int gm = m0 + r;
        if (gm < M) {
            a1R[it] = *(const uint4*)&g_T1[(size_t)gm * 512 + qc * 4];
            a2R[it] = *(const uint4*)&g_T2[(size_t)gm * 512 + qc * 4];
        } else { a1R[it] = zero4; a2R[it] = zero4; }
    }
#pragma unroll
    for (int it = 0; it < 6; it++)
        bR[it] = g_WB[tid + 128 * it];

    for (int kc = 0; kc < 32; kc++) {
        __syncthreads();
#pragma unroll
        for (int it = 0; it < 2; it++) {
            int idx = tid + 128 * it;
            int r = idx >> 2, qc = idx & 3;
            *(uint4*)&A1s[r * ASTR + qc * 4] = a1R[it];
            *(uint4*)&A2s[r * ASTR + qc * 4] = a2R[it];
        }
#pragma unroll
        for (int it = 0; it < 6; it++)
            Bs[tid + 128 * it] = bR[it];
        __syncthreads();

        if (kc < 31) {
            int kn = kc + 1;
#pragma unroll
            for (int it = 0; it < 2; it++) {
                int idx = tid + 128 * it;
                int r = idx >> 2, qc = idx & 3;
                int gm = m0 + r;
                if (gm < M) {
                    a1R[it] = *(const uint4*)&g_T1[(size_t)gm * 512 + kn * 16 + qc * 4];
                    a2R[it] = *(const uint4*)&g_T2[(size_t)gm * 512 + kn * 16 + qc * 4];
                } else { a1R[it] = zero4; a2R[it] = zero4; }
            }
#pragma unroll
            for (int it = 0; it < 6; it++)
                bR[it] = g_WB[kn * 768 + tid + 128 * it];
        }

#pragma unroll
        for (int ks = 0; ks < 2; ks++) {
            int ar = (wid * 16 + (lane >> 2)) * ASTR + ks * 8 + (lane & 3);
            uint32_t a10 = A1s[ar];
            uint32_t a11 = A1s[ar + 8 * ASTR];
            uint32_t a12 = A1s[ar + 4];
            uint32_t a13 = A1s[ar + 8 * ASTR + 4];
            uint32_t a20 = A2s[ar];
            uint32_t a21 = A2s[ar + 8 * ASTR];
            uint32_t a22 = A2s[ar + 4];
            uint32_t a23 = A2s[ar + 8 * ASTR + 4];
#pragma unroll
            for (int j = 0; j < 12; j++) {
                uint4 b = Bs[(ks * 12 + j) * 32 + lane];
                MMA_BF16(acc[j], a10, a11, a12, a13, b.x, b.y);
                MMA_BF16(acc[j], a10, a11, a12, a13, b.z, b.w);
                MMA_BF16(acc[j], a20, a21, a22, a23, b.x, b.y);
            }
        }
    }

    // ---- activation: h fragments -> y, bf16-split into Y1/Y2 smem
    int r0 = wid * 16 + (lane >> 2);
#pragma unroll
    for (int half = 0; half < 2; half++) {
        int row = r0 + half * 8;
#pragma unroll
        for (int j = 0; j < 8; j++) {
            float v0, v1;
            if (j < 4) {
                float s0 = acc[j][half * 2] * SCALE1;
                float s1 = acc[j][half * 2 + 1] * SCALE1;
                if (j < 2) { v0 = fmaxf(s0, 0.f); v1 = fmaxf(s1, 0.f); }
                else       { v0 = fabsf(s0);      v1 = fabsf(s1); }
            } else {
                float g0 = acc[j][half * 2] * SCALE1;
                float g1 = acc[j][half * 2 + 1] * SCALE1;
                float q0 = acc[j + 4][half * 2] * SCALE1;
                float q1 = acc[j + 4][half * 2 + 1] * SCALE1;
                float a0, a1;
                if ((j & 1) == 0) { a0 = fmaxf(g0, 0.f); a1 = fmaxf(g1, 0.f); }
                else              { a0 = tanhf(g0);      a1 = tanhf(g1); }
                v0 = a0 * q0; v1 = a1 * q1;
            }
            float h0 = bf_round(v0), h1 = bf_round(v1);
            int widx = row * 36 + j * 4 + (lane & 3);
            Y1[widx] = pack_bf2(h0, h1);
            Y2[widx] = pack_bf2(v0 - h0, v1 - h1);
        }
    }
    __syncthreads();

    // ---- GEMM2: z = y @ W2b^T (K=64, N=256), bf16 output
#pragma unroll
    for (int nh = 0; nh < 2; nh++) {
        float zac[16][4];
#pragma unroll
        for (int j = 0; j < 16; j++)
#pragma unroll
            for (int q = 0; q < 4; q++) zac[j][q] = 0.f;

#pragma unroll
        for (int ks = 0; ks < 4; ks++) {
            int aw = (wid * 16 + (lane >> 2)) * 36 + ks * 8 + (lane & 3);
            uint32_t a10 = Y1[aw];
            uint32_t a11 = Y1[aw + 8 * 36];
            uint32_t a12 = Y1[aw + 4];
            uint32_t a13 = Y1[aw + 8 * 36 + 4];
            uint32_t a20 = Y2[aw];
            uint32_t a21 = Y2[aw + 8 * 36];
            uint32_t a22 = Y2[aw + 4];
            uint32_t a23 = Y2[aw + 8 * 36 + 4];
#pragma unroll
            for (int j = 0; j < 16; j++) {
                uint4 b = g_WB2[((nh * 16 + j) * 4 + ks) * 32 + lane];
                MMA_BF16(zac[j], a10, a11, a12, a13, b.x, b.y);
                MMA_BF16(zac[j], a10, a11, a12, a13, b.z, b.w);
                MMA_BF16(zac[j], a20, a21, a22, a23, b.x, b.y);
            }
        }
        int rr = lane >> 2, c2 = (lane & 3) * 2;
        int gm0 = m0 + wid * 16 + rr;
#pragma unroll
        for (int j = 0; j < 16; j++) {
            int col = nh * 128 + j * 8 + c2;
            if (gm0 < M)
                *(__nv_bfloat162*)&g_zb[(size_t)gm0 * 256 + col] =
                    __floats2bfloat162_rn(zac[j][0], zac[j][1]);
            if (gm0 + 8 < M)
                *(__nv_bfloat162*)&g_zb[(size_t)(gm0 + 8) * 256 + col] =
                    __floats2bfloat162_rn(zac[j][2], zac[j][3]);
        }
    }
}

// ---------------------------------------------------------------------------
// K8: final pass, warp per SRC node; z (bf16) in registers; atomic to out
// ---------------------------------------------------------------------------
__global__ void __launch_bounds__(256) k_final(const float* __restrict__ W2a,
                                               float* __restrict__ out, int N)
{
    __shared__ float sW[768];
    for (int i = threadIdx.x; i < 768; i += 256) sW[i] = W2a[i];
    __syncthreads();

    int w = blockIdx.x * 8 + (threadIdx.x >> 5);
    int lane = threadIdx.x & 31;
    if (w >= N) return;
    int beg = g_off2[w], end = g_off2[w + 1];
    if (beg == end) return;

    float w0[8], w1[8], w2[8], zr[8];
    const __nv_bfloat16* zp = &g_zb[(size_t)w * 256];
#pragma unroll
    for (int j = 0; j < 8; j++) {
        int c = j * 32 + lane;
        w0[j] = sW[c]; w1[j] = sW[256 + c]; w2[j] = sW[512 + c];
        zr[j] = __bfloat162float(zp[c]);
    }

    for (int i = beg; i < end; i++) {
        float4 bs = *(const float4*)&g_basis2S[(size_t)i * 4];
        int dst = g_dst2S[i];
        float sum = 0.f;
#pragma unroll
        for (int j = 0; j < 8; j++) {
            float h2 = fmaxf(fmaf(bs.x, w0[j], fmaf(bs.y, w1[j], bs.z * w2[j])), 0.f);
            sum = fmaf(h2, zr[j], sum);
        }
#pragma unroll
        for (int o = 16; o > 0; o >>= 1)
            sum += __shfl_down_sync(0xffffffffu, sum, o);
        if (lane == 0) atomicAdd(&out[dst], sum * SCALE2);
    }
}

// ---------------------------------------------------------------------------
// Launch
// ---------------------------------------------------------------------------
extern "C" void kernel_launch(void* const* d_in, const int* in_sizes, int n_in,
                              void* d_out, int out_size)
{
    const float* edge_vec = (const float*)d_in[0];
    const float* edge_len = (const float*)d_in[1];
    const float* W1a      = (const float*)d_in[2];
    const float* W1b      = (const float*)d_in[3];
    const float* W2a      = (const float*)d_in[4];
    const float* W2b      = (const float*)d_in[5];
    const int*   esrc     = (const int*)d_in[6];
    const int*   edst     = (const int*)d_in[7];
    float* out = (float*)d_out;

    int E = in_sizes[1];
    int N = out_size;
    if (E > EMAX) E = EMAX;
    if (N > NMAX) N = NMAX;

    int nbE = (E + 255) / 256;
    int nbScan = (N + 1023) / 1024;   // 25

    k_zero <<<(N + 255) / 256, 256>>>(out, N);
    k_histR<<<nbE + 96 + 16, 256>>>(edst, esrc, E, nbE, W1b, W2b);
    k_scan <<<dim3(nbScan, 2), 1024>>>(E, N);
    k_sort <<<nbE, 256>>>(edst, esrc, edge_len, edge_vec, E);
    k_x    <<<(N + 15) / 16, 256>>>(N);
    k_dotsb<<<nbE, 256>>>(E);
    k_buildT<<<(N + 7) / 8, 256>>>(W1a, N);
    k_gemm_fused<<<(N + 63) / 64, 128>>>(N);
    k_final<<<(N + 7) / 8, 256>>>(W2a, out, N);
}

// round 9
// speedup vs baseline: 2.0398x; 1.0088x over previous
#include <cuda_runtime.h>
#include <cuda_bf16.h>
#include <math.h>
#include <stdint.h>

#define EMAX 250000
#define NMAX 25000

#define INV_NN   0.51298917604257706f   // 1/sqrt(3.8)
#define INV3     0.57735026918962576f
#define INV112   0.89285714285714285f   // 1/1.12
#define S3       1.7320508075688772f
#define S5       2.2360679774997896f
#define S7       2.6457513110645907f
#define S15      3.8729833462074170f
#define S105     10.246950765959598f
#define C358     2.0916500663351889f
#define C218     1.6201851746019651f
#define RS3      0.57735026918962576f
#define RS5      0.44721359549995794f
#define RS7      0.37796447300922720f
#define SCALE1   (INV3 * 0.5f / 16.0f * INV_NN)
#define SCALE2   (INV3 / 128.0f * INV_NN)

// ---------------------------------------------------------------------------
// Scratch
// ---------------------------------------------------------------------------
__device__ __align__(16) float g_shS    [EMAX * 16];  // dst-sorted sh
__device__ __align__(16) float g_x      [NMAX * 16];
__device__ __align__(16) float g_dotsS  [EMAX * 4];   // dst-sorted dots
__device__ __align__(16) float g_basisS [EMAX * 4];   // dst-sorted basis
__device__ __align__(16) float g_basis2S[EMAX * 4];   // src-sorted basis
__device__ int   g_hist [NMAX];
__device__ int   g_hist2[NMAX];
__device__ int   g_off  [NMAX + 1];
__device__ int   g_off2 [NMAX + 1];
__device__ int   g_r1   [EMAX];   // rank of edge among same-dst
__device__ int   g_r2   [EMAX];   // rank of edge among same-src
__device__ volatile int g_part[64];
__device__ volatile int g_flag[64];
__device__ int   g_srcS [EMAX];   // dst-sorted: src of edge
__device__ int   g_dst2S[EMAX];   // src-sorted: dst of edge
__device__ __align__(16) uint32_t g_T1 [(size_t)NMAX * 512];
__device__ __align__(16) uint32_t g_T2 [(size_t)NMAX * 512];
__device__ __align__(16) uint4 g_WB  [24576];  // W1b frag hi/lo
__device__ __align__(16) uint4 g_WB2 [4096];   // W2b frag hi/lo
__device__ __align__(16) float g_z   [(size_t)NMAX * 256];

// ---------------------------------------------------------------------------
// helpers
// ---------------------------------------------------------------------------
#define MMA_BF16(d, a0, a1, a2, a3, b0, b1)                                   \
    asm volatile("mma.sync.aligned.m16n8k16.row.col.f32.bf16.bf16.f32 "       \
        "{%0,%1,%2,%3},{%4,%5,%6,%7},{%8,%9},{%0,%1,%2,%3};"                  \
        : "+f"((d)[0]), "+f"((d)[1]), "+f"((d)[2]), "+f"((d)[3])              \
        : "r"(a0), "r"(a1), "r"(a2), "r"(a3), "r"(b0), "r"(b1))

__device__ __forceinline__ uint32_t pack_bf2(float a, float b) {
    __nv_bfloat162 t = __floats2bfloat162_rn(a, b);
    return *(uint32_t*)&t;
}
__device__ __forceinline__ float bf_round(float v) {
    __nv_bfloat16 t = __float2bfloat16_rn(v);
    return __bfloat162float(t);
}

// ---------------------------------------------------------------------------
// K0: zero histograms + out + scan flags
// ---------------------------------------------------------------------------
__global__ void k_zero(float* __restrict__ out, int N)
{
    int i = blockIdx.x * blockDim.x + threadIdx.x;
    if (i < N) { g_hist[i] = 0; g_hist2[i] = 0; out[i] = 0.f; }
    if (i < 64) { g_flag[i] = 0; g_part[i] = 0; }
}

// ---------------------------------------------------------------------------
// K1: histograms (recording ranks) + weight reorders
// ---------------------------------------------------------------------------
__global__ void k_histR(const int* __restrict__ edst,
                        const int* __restrict__ esrc, int E, int nbE,
                        const float* __restrict__ W1b,
                        const float* __restrict__ W2b)
{
    int b = blockIdx.x;
    int tid = threadIdx.x;
    if (b < nbE) {
        int e = b * 256 + tid;
        if (e < E) {
            g_r1[e] = atomicAdd(&g_hist[edst[e]], 1);
            g_r2[e] = atomicAdd(&g_hist2[esrc[e]], 1);
        }
        return;
    }
    if (b < nbE + 96) {
        // W1b -> bf16 hi/lo frag order (m16n8k16 B operand)
        int idx = (b - nbE) * 256 + tid;
        int lane = idx & 31;
        int t = idx >> 5;
        int j = t % 12;
        int t2 = t / 12;
        int n = j * 8 + (lane >> 2);
        int kbase = t2 * 16 + (lane & 3) * 2;
        float v[4], h[4];
        int kks[4] = {kbase, kbase + 1, kbase + 8, kbase + 9};
#pragma unroll
        for (int q = 0; q < 4; q++) {
            int kk = kks[q];
            int c = kk >> 2, p = kk & 3;
            v[q] = W1b[c * 384 + p * 96 + n];
            h[q] = bf_round(v[q]);
        }
        uint4 o;
        o.x = pack_bf2(h[0], h[1]);
        o.y = pack_bf2(h[2], h[3]);
        o.z = pack_bf2(v[0] - h[0], v[1] - h[1]);
        o.w = pack_bf2(v[2] - h[2], v[3] - h[3]);
        g_WB[idx] = o;
        return;
    }
    {
        // W2b -> bf16 hi/lo frag order
        int idx = (b - nbE - 96) * 256 + tid;
        int lane = idx & 31;
        int t = idx >> 5;
        int ks = t & 3;
        int j  = t >> 2;
        int n = j * 8 + (lane >> 2);
        int k0 = ks * 16 + (lane & 3) * 2;
        float v00 = W2b[n * 64 + k0],     v01 = W2b[n * 64 + k0 + 1];
        float v10 = W2b[n * 64 + k0 + 8], v11 = W2b[n * 64 + k0 + 9];
        float h00 = bf_round(v00), h01 = bf_round(v01);
        float h10 = bf_round(v10), h11 = bf_round(v11);
        uint4 o;
        o.x = pack_bf2(h00, h01);
        o.y = pack_bf2(h10, h11);
        o.z = pack_bf2(v00 - h00, v01 - h01);
        o.w = pack_bf2(v10 - h10, v11 - h11);
        g_WB2[idx] = o;
    }
}

// ---------------------------------------------------------------------------
// K2: single-kernel exclusive scan with decoupled block prefix
// ---------------------------------------------------------------------------
__global__ void __launch_bounds__(1024) k_scan(int E, int N)
{
    int y = blockIdx.y;
    const int* hist = y ? g_hist2 : g_hist;
    int* off = y ? g_off2 : g_off;
    int b = blockIdx.x, t = threadIdx.x;
    int lane = t & 31, wid = t >> 5;
    int idx = b * 1024 + t;
    int v = (idx < N) ? hist[idx] : 0;
    int xv = v;
#pragma unroll
    for (int o = 1; o < 32; o <<= 1) {
        int tt = __shfl_up_sync(0xffffffffu, xv, o);
        if (lane >= o) xv += tt;
    }
    __shared__ int wsum[32];
    __shared__ int wpre[32];
    __shared__ int spre;
    if (lane == 31) wsum[wid] = xv;
    __syncthreads();
    if (wid == 0) {
        int wv = wsum[lane];
        int xs = wv;
#pragma unroll
        for (int o = 1; o < 32; o <<= 1) {
            int tt = __shfl_up_sync(0xffffffffu, xs, o);
            if (lane >= o) xs += tt;
        }
        wpre[lane] = xs - wv;
    }
    __syncthreads();
    int incl = xv + wpre[wid];
    if (t == 1023) {
        g_part[y * 32 + b] = incl;
        __threadfence();
        g_flag[y * 32 + b] = 1;
    }
    if (wid == 1) {
        int pv = 0;
        if (lane < b) {
            while (g_flag[y * 32 + lane] == 0) { }
            pv = g_part[y * 32 + lane];
        }
#pragma unroll
        for (int o = 16; o > 0; o >>= 1)
            pv += __shfl_down_sync(0xffffffffu, pv, o);
        if (lane == 0) spre = pv;
    }
    __syncthreads();
    int val = incl - v + spre;
    if (idx < N) off[idx] = val;
    if (idx == N) off[N] = E;
}

// ---------------------------------------------------------------------------
// K3: fused sort (NO atomics: pos = off[key] + precomputed rank)
// ---------------------------------------------------------------------------
__global__ void k_sort(const int*   __restrict__ edst,
                       const int*   __restrict__ esrc,
                       const float* __restrict__ edge_len,
                       const float* __restrict__ edge_vec, int E)
{
    int e = blockIdx.x * blockDim.x + threadIdx.x;
    if (e >= E) return;
    int d = edst[e], s = esrc[e];
    int pos  = g_off [d] + g_r1[e];
    int pos2 = g_off2[s] + g_r2[e];

    float len = edge_len[e];
    float t0 = len * 0.5f;
    float t1 = (len - 2.0f) * 0.5f;
    float t2 = (len - 4.0f) * 0.5f;
    float4 bs = make_float4(expf(-t0 * t0) * INV112, expf(-t1 * t1) * INV112,
                            expf(-t2 * t2) * INV112, 0.f);
    *(float4*)&g_basisS [(size_t)pos  * 4] = bs;
    *(float4*)&g_basis2S[(size_t)pos2 * 4] = bs;
    g_srcS[pos]   = s;
    g_dst2S[pos2] = d;

    float x = edge_vec[e * 3 + 0];
    float y = edge_vec[e * 3 + 1];
    float z = edge_vec[e * 3 + 2];
    float inv = 1.0f / (sqrtf(x * x + y * y + z * z) + 1e-12f);
    x *= inv; y *= inv; z *= inv;
    float x2 = x * x, y2 = y * y, z2 = z * z;

    float4* shp = (float4*)&g_shS[(size_t)pos * 16];
    shp[0] = make_float4(1.0f, S3 * x, S3 * y, S3 * z);
    shp[1] = make_float4(S15 * x * z, S15 * x * y,
                         0.5f * S5 * (2.0f * y2 - x2 - z2), S15 * y * z);
    shp[2] = make_float4(0.5f * S15 * (z2 - x2),
                         C358 * x * (3.0f * z2 - x2),
                         S105 * x * y * z,
                         C218 * x * (4.0f * y2 - z2 - x2));
    shp[3] = make_float4(0.5f * S7 * y * (2.0f * y2 - 3.0f * z2 - 3.0f * x2),
                         C218 * z * (4.0f * y2 - z2 - x2),
                         0.5f * S105 * y * (z2 - x2),
                         C358 * z * (z2 - 3.0f * x2));
}

// ---------------------------------------------------------------------------
// K4: x[n,c] gather-sum over contiguous dst-sorted sh
// ---------------------------------------------------------------------------
__global__ void __launch_bounds__(256) k_x(int N)
{
    int n = blockIdx.x * 16 + (threadIdx.x >> 4);
    int c = threadIdx.x & 15;
    if (n >= N) return;
    int beg = g_off[n], end = g_off[n + 1];
    float acc = 0.f;
    for (int i = beg; i < end; i++)
        acc += g_shS[(size_t)i * 16 + c];
    g_x[n * 16 + c] = acc;
}

// ---------------------------------------------------------------------------
// K5: per-edge dots (dst-sorted streams)
// ---------------------------------------------------------------------------
__global__ void k_dotsb(int E)
{
    int i = blockIdx.x * blockDim.x + threadIdx.x;
    if (i >= E) return;
    int src = g_srcS[i];
    const float4* shp = (const float4*)&g_shS[(size_t)i * 16];
    const float4* xp  = (const float4*)&g_x[(size_t)src * 16];
    float4 s0 = shp[0], s1 = shp[1], s2 = shp[2], s3 = shp[3];
    float4 x0 = xp[0],  x1 = xp[1],  x2 = xp[2],  x3 = xp[3];

    float d0 = x0.x * s0.x;
    float d1 = (x0.y * s0.y + x0.z * s0.z + x0.w * s0.w) * RS3;
    float d2 = (x1.x * s1.x + x1.y * s1.y + x1.z * s1.z + x1.w * s1.w + x2.x * s2.x) * RS5;
    float d3 = (x2.y * s2.y + x2.z * s2.z + x2.w * s2.w +
                x3.x * s3.x + x3.y * s3.y + x3.z * s3.z + x3.w * s3.w) * RS7;
    *(float4*)&g_dotsS[(size_t)i * 4] =
        make_float4(d0 * INV_NN, d1 * INV_NN, d2 * INV_NN, d3 * INV_NN);
}

// ---------------------------------------------------------------------------
// K6: build T (streaming); store bf16 hi/lo planes
// ---------------------------------------------------------------------------
__global__ void __launch_bounds__(256) k_buildT(const float* __restrict__ W1a, int N)
{
    __shared__ float sW[768];
    for (int i = threadIdx.x; i < 768; i += 256) sW[i] = W1a[i];
    __syncthreads();

    int w = blockIdx.x * 8 + (threadIdx.x >> 5);
    int lane = threadIdx.x & 31;
    if (w >= N) return;
    int beg = g_off[w], end = g_off[w + 1];

    float wa0[8], wa1[8], wa2[8];
#pragma unroll
    for (int j = 0; j < 8; j++) {
        int c = j * 32 + lane;
        wa0[j] = sW[c]; wa1[j] = sW[256 + c]; wa2[j] = sW[512 + c];
    }
    float4 acc[8];
#pragma unroll
    for (int j = 0; j < 8; j++) acc[j] = make_float4(0.f, 0.f, 0.f, 0.f);

    for (int i = beg; i < end; i++) {
        float4 bs = *(const float4*)&g_basisS[(size_t)i * 4];
        float4 dt = *(const float4*)&g_dotsS[(size_t)i * 4];
#pragma unroll
        for (int j = 0; j < 8; j++) {
            float h1 = fmaxf(fmaf(bs.x, wa0[j], fmaf(bs.y, wa1[j], bs.z * wa2[j])), 0.f);
            acc[j].x = fmaf(h1, dt.x, acc[j].x);
            acc[j].y = fmaf(h1, dt.y, acc[j].y);
            acc[j].z = fmaf(h1, dt.z, acc[j].z);
            acc[j].w = fmaf(h1, dt.w, acc[j].w);
        }
    }
    uint32_t* t1 = &g_T1[(size_t)w * 512];
    uint32_t* t2 = &g_T2[(size_t)w * 512];
#pragma unroll
    for (int j = 0; j < 8; j++) {
        int idx = j * 32 + lane;
        float4 v = acc[j];
        float hx = bf_round(v.x), hy = bf_round(v.y);
        float hz = bf_round(v.z), hw = bf_round(v.w);
        uint2 w1 = make_uint2(pack_bf2(hx, hy), pack_bf2(hz, hw));
        uint2 w2 = make_uint2(pack_bf2(v.x - hx, v.y - hy),
                              pack_bf2(v.z - hz, v.w - hw));
        *(uint2*)&t1[idx * 2] = w1;
        *(uint2*)&t2[idx * 2] = w2;
    }
}

// ---------------------------------------------------------------------------
// K7: fused GEMM1 (h) -> activation (y) -> GEMM2 (z, f32 out)
// ---------------------------------------------------------------------------
#define ASTR 20

__global__ void __launch_bounds__(128) k_gemm_fused(int M)
{
    __shared__ uint32_t A1s[64 * ASTR];
    __shared__ uint32_t A2s[64 * ASTR];
    __shared__ uint4    Bs[768];
    __shared__ uint32_t Y1[64 * 36];
    __shared__ uint32_t Y2[64 * 36];

    int tid = threadIdx.x, wid = tid >> 5, lane = tid & 31;
    int m0 = blockIdx.x * 64;

    float acc[12][4];
#pragma unroll
    for (int j = 0; j < 12; j++)
#pragma unroll
        for (int q = 0; q < 4; q++) acc[j][q] = 0.f;

    uint4 a1R[2], a2R[2], bR[6];
    const uint4 zero4 = make_uint4(0u, 0u, 0u, 0u);

#pragma unroll
    for (int it = 0; it < 2; it++) {
        int idx = tid + 128 * it;
        int r = idx >> 2, qc = idx & 3;
        int gm = m0 + r;
        if (gm < M) {
            a1R[it] = *(const uint4*)&g_T1[(size_t)gm * 512 + qc * 4];
            a2R[it] = *(const uint4*)&g_T2[(size_t)gm * 512 + qc * 4];
        } else { a1R[it] = zero4; a2R[it] = zero4; }
    }
#pragma unroll
    for (int it = 0; it < 6; it++)
        bR[it] = g_WB[tid + 128 * it];

    for (int kc = 0; kc < 32; kc++) {
        __syncthreads();
#pragma unroll
        for (int it = 0; it < 2; it++) {
            int idx = tid + 128 * it;
            int r = idx >> 2, qc = idx & 3;
            *(uint4*)&A1s[r * ASTR + qc * 4] = a1R[it];
            *(uint4*)&A2s[r * ASTR + qc * 4] = a2R[it];
        }
#pragma unroll
        for (int it = 0; it < 6; it++)
            Bs[tid + 128 * it] = bR[it];
        __syncthreads();

        if (kc < 31) {
            int kn = kc + 1;
#pragma unroll
            for (int it = 0; it < 2; it++) {
                int idx = tid + 128 * it;
                int r = idx >> 2, qc = idx & 3;
                int gm = m0 + r;
                if (gm < M) {
                    a1R[it] = *(const uint4*)&g_T1[(size_t)gm * 512 + kn * 16 + qc * 4];
                    a2R[it] = *(const uint4*)&g_T2[(size_t)gm * 512 + kn * 16 + qc * 4];
                } else { a1R[it] = zero4; a2R[it] = zero4; }
            }
#pragma unroll
            for (int it = 0; it < 6; it++)
                bR[it] = g_WB[kn * 768 + tid + 128 * it];
        }

#pragma unroll
        for (int ks = 0; ks < 2; ks++) {
            int ar = (wid * 16 + (lane >> 2)) * ASTR + ks * 8 + (lane & 3);
            uint32_t a10 = A1s[ar];
            uint32_t a11 = A1s[ar + 8 * ASTR];
            uint32_t a12 = A1s[ar + 4];
            uint32_t a13 = A1s[ar + 8 * ASTR + 4];
            uint32_t a20 = A2s[ar];
            uint32_t a21 = A2s[ar + 8 * ASTR];
            uint32_t a22 = A2s[ar + 4];
            uint32_t a23 = A2s[ar + 8 * ASTR + 4];
#pragma unroll
            for (int j = 0; j < 12; j++) {
                uint4 b = Bs[(ks * 12 + j) * 32 + lane];
                MMA_BF16(acc[j], a10, a11, a12, a13, b.x, b.y);
                MMA_BF16(acc[j], a10, a11, a12, a13, b.z, b.w);
                MMA_BF16(acc[j], a20, a21, a22, a23, b.x, b.y);
            }
        }
    }

    // ---- activation: h fragments -> y, bf16-split into Y1/Y2 smem
    int r0 = wid * 16 + (lane >> 2);
#pragma unroll
    for (int half = 0; half < 2; half++) {
        int row = r0 + half * 8;
#pragma unroll
        for (int j = 0; j < 8; j++) {
            float v0, v1;
            if (j < 4) {
                float s0 = acc[j][half * 2] * SCALE1;
                float s1 = acc[j][half * 2 + 1] * SCALE1;
                if (j < 2) { v0 = fmaxf(s0, 0.f); v1 = fmaxf(s1, 0.f); }
                else       { v0 = fabsf(s0);      v1 = fabsf(s1); }
            } else {
                float g0 = acc[j][half * 2] * SCALE1;
                float g1 = acc[j][half * 2 + 1] * SCALE1;
                float q0 = acc[j + 4][half * 2] * SCALE1;
                float q1 = acc[j + 4][half * 2 + 1] * SCALE1;
                float a0, a1;
                if ((j & 1) == 0) { a0 = fmaxf(g0, 0.f); a1 = fmaxf(g1, 0.f); }
                else              { a0 = tanhf(g0);      a1 = tanhf(g1); }
                v0 = a0 * q0; v1 = a1 * q1;
            }
            float h0 = bf_round(v0), h1 = bf_round(v1);
            int widx = row * 36 + j * 4 + (lane & 3);
            Y1[widx] = pack_bf2(h0, h1);
            Y2[widx] = pack_bf2(v0 - h0, v1 - h1);
        }
    }
    __syncthreads();

    // ---- GEMM2: z = y @ W2b^T (K=64, N=256), f32 output
#pragma unroll
    for (int nh = 0; nh < 2; nh++) {
        float zac[16][4];
#pragma unroll
        for (int j = 0; j < 16; j++)
#pragma unroll
            for (int q = 0; q < 4; q++) zac[j][q] = 0.f;

#pragma unroll
        for (int ks = 0; ks < 4; ks++) {
            int aw = (wid * 16 + (lane >> 2)) * 36 + ks * 8 + (lane & 3);
            uint32_t a10 = Y1[aw];
            uint32_t a11 = Y1[aw + 8 * 36];
            uint32_t a12 = Y1[aw + 4];
            uint32_t a13 = Y1[aw + 8 * 36 + 4];
            uint32_t a20 = Y2[aw];
            uint32_t a21 = Y2[aw + 8 * 36];
            uint32_t a22 = Y2[aw + 4];
            uint32_t a23 = Y2[aw + 8 * 36 + 4];
#pragma unroll
            for (int j = 0; j < 16; j++) {
                uint4 b = g_WB2[((nh * 16 + j) * 4 + ks) * 32 + lane];
                MMA_BF16(zac[j], a10, a11, a12, a13, b.x, b.y);
                MMA_BF16(zac[j], a10, a11, a12, a13, b.z, b.w);
                MMA_BF16(zac[j], a20, a21, a22, a23, b.x, b.y);
            }
        }
        int rr = lane >> 2, c2 = (lane & 3) * 2;
        int gm0 = m0 + wid * 16 + rr;
#pragma unroll
        for (int j = 0; j < 16; j++) {
            int col = nh * 128 + j * 8 + c2;
            if (gm0 < M)
                *(float2*)&g_z[(size_t)gm0 * 256 + col] =
                    make_float2(zac[j][0], zac[j][1]);
            if (gm0 + 8 < M)
                *(float2*)&g_z[(size_t)(gm0 + 8) * 256 + col] =
                    make_float2(zac[j][2], zac[j][3]);
        }
    }
}

// ---------------------------------------------------------------------------
// K8: final pass, warp per SRC node; z (f32) in registers; atomic to out
// ---------------------------------------------------------------------------
__global__ void __launch_bounds__(256) k_final(const float* __restrict__ W2a,
                                               float* __restrict__ out, int N)
{
    __shared__ float sW[768];
    for (int i = threadIdx.x; i < 768; i += 256) sW[i] = W2a[i];
    __syncthreads();

    int w = blockIdx.x * 8 + (threadIdx.x >> 5);
    int lane = threadIdx.x & 31;
    if (w >= N) return;
    int beg = g_off2[w], end = g_off2[w + 1];
    if (beg == end) return;

    float w0[8], w1[8], w2[8], zr[8];
    const float* zp = &g_z[(size_t)w * 256];
#pragma unroll
    for (int j = 0; j < 8; j++) {
        int c = j * 32 + lane;
        w0[j] = sW[c]; w1[j] = sW[256 + c]; w2[j] = sW[512 + c];
        zr[j] = zp[c];
    }

    for (int i = beg; i < end; i++) {
        float4 bs = *(const float4*)&g_basis2S[(size_t)i * 4];
        int dst = g_dst2S[i];
        float sum = 0.f;
#pragma unroll
        for (int j = 0; j < 8; j++) {
            float h2 = fmaxf(fmaf(bs.x, w0[j], fmaf(bs.y, w1[j], bs.z * w2[j])), 0.f);
            sum = fmaf(h2, zr[j], sum);
        }
#pragma unroll
        for (int o = 16; o > 0; o >>= 1)
            sum += __shfl_down_sync(0xffffffffu, sum, o);
        if (lane == 0) atomicAdd(&out[dst], sum * SCALE2);
    }
}

// ---------------------------------------------------------------------------
// Launch
// ---------------------------------------------------------------------------
extern "C" void kernel_launch(void* const* d_in, const int* in_sizes, int n_in,
                              void* d_out, int out_size)
{
    const float* edge_vec = (const float*)d_in[0];
    const float* edge_len = (const float*)d_in[1];
    const float* W1a      = (const float*)d_in[2];
    const float* W1b      = (const float*)d_in[3];
    const float* W2a      = (const float*)d_in[4];
    const float* W2b      = (const float*)d_in[5];
    const int*   esrc     = (const int*)d_in[6];
    const int*   edst     = (const int*)d_in[7];
    float* out = (float*)d_out;

    int E = in_sizes[1];
    int N = out_size;
    if (E > EMAX) E = EMAX;
    if (N > NMAX) N = NMAX;

    int nbE = (E + 255) / 256;
    int nbScan = (N + 1023) / 1024;   // 25

    k_zero <<<(N + 255) / 256, 256>>>(out, N);
    k_histR<<<nbE + 96 + 16, 256>>>(edst, esrc, E, nbE, W1b, W2b);
    k_scan <<<dim3(nbScan, 2), 1024>>>(E, N);
    k_sort <<<nbE, 256>>>(edst, esrc, edge_len, edge_vec, E);
    k_x    <<<(N + 15) / 16, 256>>>(N);
    k_dotsb<<<nbE, 256>>>(E);
    k_buildT<<<(N + 7) / 8, 256>>>(W1a, N);
    k_gemm_fused<<<(N + 63) / 64, 128>>>(N);
    k_final<<<(N + 7) / 8, 256>>>(W2a, out, N);
}

// round 10
// speedup vs baseline: 2.2038x; 1.0804x over previous
#include <cuda_runtime.h>
#include <cuda_bf16.h>
#include <math.h>
#include <stdint.h>

#define EMAX 250000
#define NMAX 25000

#define INV_NN   0.51298917604257706f   // 1/sqrt(3.8)
#define INV3     0.57735026918962576f
#define INV112   0.89285714285714285f   // 1/1.12
#define S3       1.7320508075688772f
#define S5       2.2360679774997896f
#define S7       2.6457513110645907f
#define S15      3.8729833462074170f
#define S105     10.246950765959598f
#define C358     2.0916500663351889f
#define C218     1.6201851746019651f
#define RS3      0.57735026918962576f
#define RS5      0.44721359549995794f
#define RS7      0.37796447300922720f
#define SCALE1   (INV3 * 0.5f / 16.0f * INV_NN)
#define SCALE2   (INV3 / 128.0f * INV_NN)

// ---------------------------------------------------------------------------
// Scratch
// ---------------------------------------------------------------------------
__device__ __align__(16) float g_vecS   [EMAX * 4];   // dst-sorted: nx,ny,nz,srcbits
__device__ __align__(16) float g_x      [NMAX * 16];
__device__ __align__(16) float g_dotsS  [EMAX * 4];   // dst-sorted dots
__device__ __align__(16) float g_basisS [EMAX * 4];   // dst-sorted basis
__device__ __align__(16) float g_basis2S[EMAX * 4];   // src-sorted basis (+dst bits)
__device__ int   g_hist [NMAX];
__device__ int   g_hist2[NMAX];
__device__ int   g_off  [NMAX + 1];
__device__ int   g_off2 [NMAX + 1];
__device__ int   g_r1   [EMAX];
__device__ int   g_r2   [EMAX];
__device__ volatile int g_part[64];
__device__ volatile int g_flag[64];
__device__ __align__(16) uint32_t g_T1 [(size_t)NMAX * 512];
__device__ __align__(16) uint32_t g_T2 [(size_t)NMAX * 512];
__device__ __align__(16) uint4 g_WB  [24576];  // W1b frag hi/lo
__device__ __align__(16) uint4 g_WB2 [4096];   // W2b frag hi/lo
__device__ __align__(16) float g_z   [(size_t)NMAX * 256];

// ---------------------------------------------------------------------------
// helpers
// ---------------------------------------------------------------------------
#define MMA_BF16(d, a0, a1, a2, a3, b0, b1)                                   \
    asm volatile("mma.sync.aligned.m16n8k16.row.col.f32.bf16.bf16.f32 "       \
        "{%0,%1,%2,%3},{%4,%5,%6,%7},{%8,%9},{%0,%1,%2,%3};"                  \
        : "+f"((d)[0]), "+f"((d)[1]), "+f"((d)[2]), "+f"((d)[3])              \
        : "r"(a0), "r"(a1), "r"(a2), "r"(a3), "r"(b0), "r"(b1))

__device__ __forceinline__ uint32_t pack_bf2(float a, float b) {
    __nv_bfloat162 t = __floats2bfloat162_rn(a, b);
    return *(uint32_t*)&t;
}
__device__ __forceinline__ float bf_round(float v) {
    __nv_bfloat16 t = __float2bfloat16_rn(v);
    return __bfloat162float(t);
}

// sh from a normalized direction (x,y,z) -> 4 float4s
__device__ __forceinline__ void sh_eval(float x, float y, float z,
                                        float4& s0, float4& s1,
                                        float4& s2, float4& s3)
{
    float x2 = x * x, y2 = y * y, z2 = z * z;
    s0 = make_float4(1.0f, S3 * x, S3 * y, S3 * z);
    s1 = make_float4(S15 * x * z, S15 * x * y,
                     0.5f * S5 * (2.0f * y2 - x2 - z2), S15 * y * z);
    s2 = make_float4(0.5f * S15 * (z2 - x2),
                     C358 * x * (3.0f * z2 - x2),
                     S105 * x * y * z,
                     C218 * x * (4.0f * y2 - z2 - x2));
    s3 = make_float4(0.5f * S7 * y * (2.0f * y2 - 3.0f * z2 - 3.0f * x2),
                     C218 * z * (4.0f * y2 - z2 - x2),
                     0.5f * S105 * y * (z2 - x2),
                     C358 * z * (z2 - 3.0f * x2));
}

// ---------------------------------------------------------------------------
// K0: zero histograms + out + scan flags
// ---------------------------------------------------------------------------
__global__ void k_zero(float* __restrict__ out, int N)
{
    int i = blockIdx.x * blockDim.x + threadIdx.x;
    if (i < N) { g_hist[i] = 0; g_hist2[i] = 0; out[i] = 0.f; }
    if (i < 64) { g_flag[i] = 0; g_part[i] = 0; }
}

// ---------------------------------------------------------------------------
// K1: histograms (recording ranks) + weight reorders
// ---------------------------------------------------------------------------
__global__ void k_histR(const int* __restrict__ edst,
                        const int* __restrict__ esrc, int E, int nbE,
                        const float* __restrict__ W1b,
                        const float* __restrict__ W2b)
{
    int b = blockIdx.x;
    int tid = threadIdx.x;
    if (b < nbE) {
        int e = b * 256 + tid;
        if (e < E) {
            g_r1[e] = atomicAdd(&g_hist[edst[e]], 1);
            g_r2[e] = atomicAdd(&g_hist2[esrc[e]], 1);
        }
        return;
    }
    if (b < nbE + 96) {
        int idx = (b - nbE) * 256 + tid;
        int lane = idx & 31;
        int t = idx >> 5;
        int j = t % 12;
        int t2 = t / 12;
        int n = j * 8 + (lane >> 2);
        int kbase = t2 * 16 + (lane & 3) * 2;
        float v[4], h[4];
        int kks[4] = {kbase, kbase + 1, kbase + 8, kbase + 9};
#pragma unroll
        for (int q = 0; q < 4; q++) {
            int kk = kks[q];
            int c = kk >> 2, p = kk & 3;
            v[q] = W1b[c * 384 + p * 96 + n];
            h[q] = bf_round(v[q]);
        }
        uint4 o;
        o.x = pack_bf2(h[0], h[1]);
        o.y = pack_bf2(h[2], h[3]);
        o.z = pack_bf2(v[0] - h[0], v[1] - h[1]);
        o.w = pack_bf2(v[2] - h[2], v[3] - h[3]);
        g_WB[idx] = o;
        return;
    }
    {
        int idx = (b - nbE - 96) * 256 + tid;
        int lane = idx & 31;
        int t = idx >> 5;
        int ks = t & 3;
        int j  = t >> 2;
        int n = j * 8 + (lane >> 2);
        int k0 = ks * 16 + (lane & 3) * 2;
        float v00 = W2b[n * 64 + k0],     v01 = W2b[n * 64 + k0 + 1];
        float v10 = W2b[n * 64 + k0 + 8], v11 = W2b[n * 64 + k0 + 9];
        float h00 = bf_round(v00), h01 = bf_round(v01);
        float h10 = bf_round(v10), h11 = bf_round(v11);
        uint4 o;
        o.x = pack_bf2(h00, h01);
        o.y = pack_bf2(h10, h11);
        o.z = pack_bf2(v00 - h00, v01 - h01);
        o.w = pack_bf2(v10 - h10, v11 - h11);
        g_WB2[idx] = o;
    }
}

// ---------------------------------------------------------------------------
// K2: single-kernel exclusive scan with decoupled block prefix
// ---------------------------------------------------------------------------
__global__ void __launch_bounds__(1024) k_scan(int E, int N)
{
    int y = blockIdx.y;
    const int* hist = y ? g_hist2 : g_hist;
    int* off = y ? g_off2 : g_off;
    int b = blockIdx.x, t = threadIdx.x;
    int lane = t & 31, wid = t >> 5;
    int idx = b * 1024 + t;
    int v = (idx < N) ? hist[idx] : 0;
    int xv = v;
#pragma unroll
    for (int o = 1; o < 32; o <<= 1) {
        int tt = __shfl_up_sync(0xffffffffu, xv, o);
        if (lane >= o) xv += tt;
    }
    __shared__ int wsum[32];
    __shared__ int wpre[32];
    __shared__ int spre;
    if (lane == 31) wsum[wid] = xv;
    __syncthreads();
    if (wid == 0) {
        int wv = wsum[lane];
        int xs = wv;
#pragma unroll
        for (int o = 1; o < 32; o <<= 1) {
            int tt = __shfl_up_sync(0xffffffffu, xs, o);
            if (lane >= o) xs += tt;
        }
        wpre[lane] = xs - wv;
    }
    __syncthreads();
    int incl = xv + wpre[wid];
    if (t == 1023) {
        g_part[y * 32 + b] = incl;
        __threadfence();
        g_flag[y * 32 + b] = 1;
    }
    if (wid == 1) {
        int pv = 0;
        if (lane < b) {
            while (g_flag[y * 32 + lane] == 0) { }
            pv = g_part[y * 32 + lane];
        }
#pragma unroll
        for (int o = 16; o > 0; o >>= 1)
            pv += __shfl_down_sync(0xffffffffu, pv, o);
        if (lane == 0) spre = pv;
    }
    __syncthreads();
    int val = incl - v + spre;
    if (idx < N) off[idx] = val;
    if (idx == N) off[N] = E;
}

// ---------------------------------------------------------------------------
// K3: fused sort (no atomics): 3x 16B scattered stores per edge
// ---------------------------------------------------------------------------
__global__ void k_sort(const int*   __restrict__ edst,
                       const int*   __restrict__ esrc,
                       const float* __restrict__ edge_len,
                       const float* __restrict__ edge_vec, int E)
{
    int e = blockIdx.x * blockDim.x + threadIdx.x;
    if (e >= E) return;
    int d = edst[e], s = esrc[e];
    int pos  = g_off [d] + g_r1[e];
    int pos2 = g_off2[s] + g_r2[e];

    float len = edge_len[e];
    float t0 = len * 0.5f;
    float t1 = (len - 2.0f) * 0.5f;
    float t2 = (len - 4.0f) * 0.5f;
    float b0 = expf(-t0 * t0) * INV112;
    float b1 = expf(-t1 * t1) * INV112;
    float b2 = expf(-t2 * t2) * INV112;
    *(float4*)&g_basisS [(size_t)pos  * 4] = make_float4(b0, b1, b2, 0.f);
    *(float4*)&g_basis2S[(size_t)pos2 * 4] =
        make_float4(b0, b1, b2, __int_as_float(d));

    float x = edge_vec[e * 3 + 0];
    float y = edge_vec[e * 3 + 1];
    float z = edge_vec[e * 3 + 2];
    float inv = 1.0f / (sqrtf(x * x + y * y + z * z) + 1e-12f);
    *(float4*)&g_vecS[(size_t)pos * 4] =
        make_float4(x * inv, y * inv, z * inv, __int_as_float(s));
}

// ---------------------------------------------------------------------------
// K4: x[n,:] = sum of sh over the node's dst-sorted edges.
//     8 lanes per node; each lane accumulates all 16 channels; shfl reduce.
// ---------------------------------------------------------------------------
__global__ void __launch_bounds__(256) k_x(int N)
{
    int n = blockIdx.x * 32 + (threadIdx.x >> 3);
    int sl = threadIdx.x & 7;
    if (n >= N) return;
    int beg = g_off[n], end = g_off[n + 1];

    float4 a0 = make_float4(0, 0, 0, 0), a1 = a0, a2 = a0, a3 = a0;
    for (int i = beg + sl; i < end; i += 8) {
        float4 v = *(const float4*)&g_vecS[(size_t)i * 4];
        float4 s0, s1, s2, s3;
        sh_eval(v.x, v.y, v.z, s0, s1, s2, s3);
        a0.x += s0.x; a0.y += s0.y; a0.z += s0.z; a0.w += s0.w;
        a1.x += s1.x; a1.y += s1.y; a1.z += s1.z; a1.w += s1.w;
        a2.x += s2.x; a2.y += s2.y; a2.z += s2.z; a2.w += s2.w;
        a3.x += s3.x; a3.y += s3.y; a3.z += s3.z; a3.w += s3.w;
    }
    float* ap = (float*)&a0;   // a0..a3 contiguous in regs? not guaranteed;
    // reduce each component across the 8-lane segment
#pragma unroll
    for (int o = 4; o > 0; o >>= 1) {
        a0.x += __shfl_down_sync(0xffffffffu, a0.x, o, 8);
        a0.y += __shfl_down_sync(0xffffffffu, a0.y, o, 8);
        a0.z += __shfl_down_sync(0xffffffffu, a0.z, o, 8);
        a0.w += __shfl_down_sync(0xffffffffu, a0.w, o, 8);
        a1.x += __shfl_down_sync(0xffffffffu, a1.x, o, 8);
        a1.y += __shfl_down_sync(0xffffffffu, a1.y, o, 8);
        a1.z += __shfl_down_sync(0xffffffffu, a1.z, o, 8);
        a1.w += __shfl_down_sync(0xffffffffu, a1.w, o, 8);
        a2.x += __shfl_down_sync(0xffffffffu, a2.x, o, 8);
        a2.y += __shfl_down_sync(0xffffffffu, a2.y, o, 8);
        a2.z += __shfl_down_sync(0xffffffffu, a2.z, o, 8);
        a2.w += __shfl_down_sync(0xffffffffu, a2.w, o, 8);
        a3.x += __shfl_down_sync(0xffffffffu, a3.x, o, 8);
        a3.y += __shfl_down_sync(0xffffffffu, a3.y, o, 8);
        a3.z += __shfl_down_sync(0xffffffffu, a3.z, o, 8);
        a3.w += __shfl_down_sync(0xffffffffu, a3.w, o, 8);
    }
    (void)ap;
    if (sl == 0) {
        float4* xp = (float4*)&g_x[(size_t)n * 16];
        xp[0] = a0; xp[1] = a1; xp[2] = a2; xp[3] = a3;
    }
}

// ---------------------------------------------------------------------------
// K5: per-edge dots (recompute sh from vecS; src packed in .w)
// ---------------------------------------------------------------------------
__global__ void k_dotsb(int E)
{
    int i = blockIdx.x * blockDim.x + threadIdx.x;
    if (i >= E) return;
    float4 v = *(const float4*)&g_vecS[(size_t)i * 4];
    int src = __float_as_int(v.w);
    float4 s0, s1, s2, s3;
    sh_eval(v.x, v.y, v.z, s0, s1, s2, s3);
    const float4* xp = (const float4*)&g_x[(size_t)src * 16];
    float4 x0 = xp[0], x1 = xp[1], x2 = xp[2], x3 = xp[3];

    float d0 = x0.x * s0.x;
    float d1 = (x0.y * s0.y + x0.z * s0.z + x0.w * s0.w) * RS3;
    float d2 = (x1.x * s1.x + x1.y * s1.y + x1.z * s1.z + x1.w * s1.w + x2.x * s2.x) * RS5;
    float d3 = (x2.y * s2.y + x2.z * s2.z + x2.w * s2.w +
                x3.x * s3.x + x3.y * s3.y + x3.z * s3.z + x3.w * s3.w) * RS7;
    *(float4*)&g_dotsS[(size_t)i * 4] =
        make_float4(d0 * INV_NN, d1 * INV_NN, d2 * INV_NN, d3 * INV_NN);
}

// ---------------------------------------------------------------------------
// K6: build T (streaming); store bf16 hi/lo planes
// ---------------------------------------------------------------------------
__global__ void __launch_bounds__(256) k_buildT(const float* __restrict__ W1a, int N)
{
    __shared__ float sW[768];
    for (int i = threadIdx.x; i < 768; i += 256) sW[i] = W1a[i];
    __syncthreads();

    int w = blockIdx.x * 8 + (threadIdx.x >> 5);
    int lane = threadIdx.x & 31;
    if (w >= N) return;
    int beg = g_off[w], end = g_off[w + 1];

    float wa0[8], wa1[8], wa2[8];
#pragma unroll
    for (int j = 0; j < 8; j++) {
        int c = j * 32 + lane;
        wa0[j] = sW[c]; wa1[j] = sW[256 + c]; wa2[j] = sW[512 + c];
    }
    float4 acc[8];
#pragma unroll
    for (int j = 0; j < 8; j++) acc[j] = make_float4(0.f, 0.f, 0.f, 0.f);

    for (int i = beg; i < end; i++) {
        float4 bs = *(const float4*)&g_basisS[(size_t)i * 4];
        float4 dt = *(const float4*)&g_dotsS[(size_t)i * 4];
#pragma unroll
        for (int j = 0; j < 8; j++) {
            float h1 = fmaxf(fmaf(bs.x, wa0[j], fmaf(bs.y, wa1[j], bs.z * wa2[j])), 0.f);
            acc[j].x = fmaf(h1, dt.x, acc[j].x);
            acc[j].y = fmaf(h1, dt.y, acc[j].y);
            acc[j].z = fmaf(h1, dt.z, acc[j].z);
            acc[j].w = fmaf(h1, dt.w, acc[j].w);
        }
    }
    uint32_t* t1 = &g_T1[(size_t)w * 512];
    uint32_t* t2 = &g_T2[(size_t)w * 512];
#pragma unroll
    for (int j = 0; j < 8; j++) {
        int idx = j * 32 + lane;
        float4 v = acc[j];
        float hx = bf_round(v.x), hy = bf_round(v.y);
        float hz = bf_round(v.z), hw = bf_round(v.w);
        uint2 w1 = make_uint2(pack_bf2(hx, hy), pack_bf2(hz, hw));
        uint2 w2 = make_uint2(pack_bf2(v.x - hx, v.y - hy),
                              pack_bf2(v.z - hz, v.w - hw));
        *(uint2*)&t1[idx * 2] = w1;
        *(uint2*)&t2[idx * 2] = w2;
    }
}

// ---------------------------------------------------------------------------
// K7: fused GEMM1 (h) -> activation (y) -> GEMM2 (z, f32 out)
// ---------------------------------------------------------------------------
#define ASTR 20

__global__ void __launch_bounds__(128) k_gemm_fused(int M)
{
    __shared__ uint32_t A1s[64 * ASTR];
    __shared__ uint32_t A2s[64 * ASTR];
    __shared__ uint4    Bs[768];
    __shared__ uint32_t Y1[64 * 36];
    __shared__ uint32_t Y2[64 * 36];

    int tid = threadIdx.x, wid = tid >> 5, lane = tid & 31;
    int m0 = blockIdx.x * 64;

    float acc[12][4];
#pragma unroll
    for (int j = 0; j < 12; j++)
#pragma unroll
        for (int q = 0; q < 4; q++) acc[j][q] = 0.f;

    uint4 a1R[2], a2R[2], bR[6];
    const uint4 zero4 = make_uint4(0u, 0u, 0u, 0u);

#pragma unroll
    for (int it = 0; it < 2; it++) {
        int idx = tid + 128 * it;
        int r = idx >> 2, qc = idx & 3;
        int gm = m0 + r;
        if (gm < M) {
            a1R[it] = *(const uint4*)&g_T1[(size_t)gm * 512 + qc * 4];
            a2R[it] = *(const uint4*)&g_T2[(size_t)gm * 512 + qc * 4];
        } else { a1R[it] = zero4; a2R[it] = zero4; }
    }
#pragma unroll
    for (int it = 0; it < 6; it++)
        bR[it] = g_WB[tid + 128 * it];

    for (int kc = 0; kc < 32; kc++) {
        __syncthreads();
#pragma unroll
        for (int it = 0; it < 2; it++) {
            int idx = tid + 128 * it;
            int r = idx >> 2, qc = idx & 3;
            *(uint4*)&A1s[r * ASTR + qc * 4] = a1R[it];
            *(uint4*)&A2s[r * ASTR + qc * 4] = a2R[it];
        }
#pragma unroll
        for (int it = 0; it < 6; it++)
            Bs[tid + 128 * it] = bR[it];
        __syncthreads();

        if (kc < 31) {
            int kn = kc + 1;
#pragma unroll
            for (int it = 0; it < 2; it++) {
                int idx = tid + 128 * it;
                int r = idx >> 2, qc = idx & 3;
                int gm = m0 + r;
                if (gm < M) {
                    a1R[it] = *(const uint4*)&g_T1[(size_t)gm * 512 + kn * 16 + qc * 4];
                    a2R[it] = *(const uint4*)&g_T2[(size_t)gm * 512 + kn * 16 + qc * 4];
                } else { a1R[it] = zero4; a2R[it] = zero4; }
            }
#pragma unroll
            for (int it = 0; it < 6; it++)
                bR[it] = g_WB[kn * 768 + tid + 128 * it];
        }

#pragma unroll
        for (int ks = 0; ks < 2; ks++) {
            int ar = (wid * 16 + (lane >> 2)) * ASTR + ks * 8 + (lane & 3);
            uint32_t a10 = A1s[ar];
            uint32_t a11 = A1s[ar + 8 * ASTR];
            uint32_t a12 = A1s[ar + 4];
            uint32_t a13 = A1s[ar + 8 * ASTR + 4];
            uint32_t a20 = A2s[ar];
            uint32_t a21 = A2s[ar + 8 * ASTR];
            uint32_t a22 = A2s[ar + 4];
            uint32_t a23 = A2s[ar + 8 * ASTR + 4];
#pragma unroll
            for (int j = 0; j < 12; j++) {
                uint4 b = Bs[(ks * 12 + j) * 32 + lane];
                MMA_BF16(acc[j], a10, a11, a12, a13, b.x, b.y);
                MMA_BF16(acc[j], a10, a11, a12, a13, b.z, b.w);
                MMA_BF16(acc[j], a20, a21, a22, a23, b.x, b.y);
            }
        }
    }

    // ---- activation: h fragments -> y, bf16-split into Y1/Y2 smem
    int r0 = wid * 16 + (lane >> 2);
#pragma unroll
    for (int half = 0; half < 2; half++) {
        int row = r0 + half * 8;
#pragma unroll
        for (int j = 0; j < 8; j++) {
            float v0, v1;
            if (j < 4) {
                float s0 = acc[j][half * 2] * SCALE1;
                float s1 = acc[j][half * 2 + 1] * SCALE1;
                if (j < 2) { v0 = fmaxf(s0, 0.f); v1 = fmaxf(s1, 0.f); }
                else       { v0 = fabsf(s0);      v1 = fabsf(s1); }
            } else {
                float g0 = acc[j][half * 2] * SCALE1;
                float g1 = acc[j][half * 2 + 1] * SCALE1;
                float q0 = acc[j + 4][half * 2] * SCALE1;
                float q1 = acc[j + 4][half * 2 + 1] * SCALE1;
                float a0, a1;
                if ((j & 1) == 0) { a0 = fmaxf(g0, 0.f); a1 = fmaxf(g1, 0.f); }
                else              { a0 = tanhf(g0);      a1 = tanhf(g1); }
                v0 = a0 * q0; v1 = a1 * q1;
            }
            float h0 = bf_round(v0), h1 = bf_round(v1);
            int widx = row * 36 + j * 4 + (lane & 3);
            Y1[widx] = pack_bf2(h0, h1);
            Y2[widx] = pack_bf2(v0 - h0, v1 - h1);
        }
    }
    __syncthreads();

    // ---- GEMM2: z = y @ W2b^T (K=64, N=256), f32 output
#pragma unroll
    for (int nh = 0; nh < 2; nh++) {
        float zac[16][4];
#pragma unroll
        for (int j = 0; j < 16; j++)
#pragma unroll
            for (int q = 0; q < 4; q++) zac[j][q] = 0.f;

#pragma unroll
        for (int ks = 0; ks < 4; ks++) {
            int aw = (wid * 16 + (lane >> 2)) * 36 + ks * 8 + (lane & 3);
            uint32_t a10 = Y1[aw];
            uint32_t a11 = Y1[aw + 8 * 36];
            uint32_t a12 = Y1[aw + 4];
            uint32_t a13 = Y1[aw + 8 * 36 + 4];
            uint32_t a20 = Y2[aw];
            uint32_t a21 = Y2[aw + 8 * 36];
            uint32_t a22 = Y2[aw + 4];
            uint32_t a23 = Y2[aw + 8 * 36 + 4];
#pragma unroll
            for (int j = 0; j < 16; j++) {
                uint4 b = g_WB2[((nh * 16 + j) * 4 + ks) * 32 + lane];
                MMA_BF16(zac[j], a10, a11, a12, a13, b.x, b.y);
                MMA_BF16(zac[j], a10, a11, a12, a13, b.z, b.w);
                MMA_BF16(zac[j], a20, a21, a22, a23, b.x, b.y);
            }
        }
        int rr = lane >> 2, c2 = (lane & 3) * 2;
        int gm0 = m0 + wid * 16 + rr;
#pragma unroll
        for (int j = 0; j < 16; j++) {
            int col = nh * 128 + j * 8 + c2;
            if (gm0 < M)
                *(float2*)&g_z[(size_t)gm0 * 256 + col] =
                    make_float2(zac[j][0], zac[j][1]);
            if (gm0 + 8 < M)
                *(float2*)&g_z[(size_t)(gm0 + 8) * 256 + col] =
                    make_float2(zac[j][2], zac[j][3]);
        }
    }
}

// ---------------------------------------------------------------------------
// K8: final pass, warp per SRC node; z (f32) in registers; atomic to out
// ---------------------------------------------------------------------------
__global__ void __launch_bounds__(256) k_final(const float* __restrict__ W2a,
                                               float* __restrict__ out, int N)
{
    __shared__ float sW[768];
    for (int i = threadIdx.x; i < 768; i += 256) sW[i] = W2a[i];
    __syncthreads();

    int w = blockIdx.x * 8 + (threadIdx.x >> 5);
    int lane = threadIdx.x & 31;
    if (w >= N) return;
    int beg = g_off2[w], end = g_off2[w + 1];
    if (beg == end) return;

    float w0[8], w1[8], w2[8], zr[8];
    const float* zp = &g_z[(size_t)w * 256];
#pragma unroll
    for (int j = 0; j < 8; j++) {
        int c = j * 32 + lane;
        w0[j] = sW[c]; w1[j] = sW[256 + c]; w2[j] = sW[512 + c];
        zr[j] = zp[c];
    }

    for (int i = beg; i < end; i++) {
        float4 bs = *(const float4*)&g_basis2S[(size_t)i * 4];
        int dst = __float_as_int(bs.w);
        float sum = 0.f;
#pragma unroll
        for (int j = 0; j < 8; j++) {
            float h2 = fmaxf(fmaf(bs.x, w0[j], fmaf(bs.y, w1[j], bs.z * w2[j])), 0.f);
            sum = fmaf(h2, zr[j], sum);
        }
#pragma unroll
        for (int o = 16; o > 0; o >>= 1)
            sum += __shfl_down_sync(0xffffffffu, sum, o);
        if (lane == 0) atomicAdd(&out[dst], sum * SCALE2);
    }
}

// ---------------------------------------------------------------------------
// Launch
// ---------------------------------------------------------------------------
extern "C" void kernel_launch(void* const* d_in, const int* in_sizes, int n_in,
                              void* d_out, int out_size)
{
    const float* edge_vec = (const float*)d_in[0];
    const float* edge_len = (const float*)d_in[1];
    const float* W1a      = (const float*)d_in[2];
    const float* W1b      = (const float*)d_in[3];
    const float* W2a      = (const float*)d_in[4];
    const float* W2b      = (const float*)d_in[5];
    const int*   esrc     = (const int*)d_in[6];
    const int*   edst     = (const int*)d_in[7];
    float* out = (float*)d_out;

    int E = in_sizes[1];
    int N = out_size;
    if (E > EMAX) E = EMAX;
    if (N > NMAX) N = NMAX;

    int nbE = (E + 255) / 256;
    int nbScan = (N + 1023) / 1024;   // 25

    k_zero <<<(N + 255) / 256, 256>>>(out, N);
    k_histR<<<nbE + 96 + 16, 256>>>(edst, esrc, E, nbE, W1b, W2b);
    k_scan <<<dim3(nbScan, 2), 1024>>>(E, N);
    k_sort <<<nbE, 256>>>(edst, esrc, edge_len, edge_vec, E);
    k_x    <<<(N + 31) / 32, 256>>>(N);
    k_dotsb<<<nbE, 256>>>(E);
    k_buildT<<<(N + 7) / 8, 256>>>(W1a, N);
    k_gemm_fused<<<(N + 63) / 64, 128>>>(N);
    k_final<<<(N + 7) / 8, 256>>>(W2a, out, N);
}